// round 1
// baseline (speedup 1.0000x reference)
#include <cuda_runtime.h>
#include <cstdint>

#define NS 5000
#define NM 100000
#define NR 2000
#define H  128
#define E_SM  2000000
#define E_RM  1000000
#define E_SIM 2000000
#define NLBL  500000

// ---------------- static device scratch (no cudaMalloc allowed) ----------------
static constexpr size_t SZ_S = (size_t)NS * H;
static constexpr size_t SZ_M = (size_t)NM * H;
static constexpr size_t SZ_R = (size_t)NR * H;

static constexpr size_t OFF_XS0   = 0;
static constexpr size_t OFF_XS1   = OFF_XS0 + SZ_S;
static constexpr size_t OFF_XR0   = OFF_XS1 + SZ_S;
static constexpr size_t OFF_XR1   = OFF_XR0 + SZ_R;
static constexpr size_t OFF_AGGS  = OFF_XR1 + SZ_R;
static constexpr size_t OFF_AGGR  = OFF_AGGS + SZ_S;
static constexpr size_t OFF_XM0   = OFF_AGGR + SZ_R;
static constexpr size_t OFF_XM1   = OFF_XM0 + SZ_M;
static constexpr size_t OFF_XW0   = OFF_XM1 + SZ_M;
static constexpr size_t OFF_XW1   = OFF_XW0 + SZ_M;
static constexpr size_t OFF_ACCM  = OFF_XW1 + SZ_M;
static constexpr size_t OFF_AGGSM = OFF_ACCM + SZ_M;
static constexpr size_t OFF_AGGRM = OFF_AGGSM + SZ_M;
static constexpr size_t OFF_WRSUM = OFF_AGGRM + SZ_M;
static constexpr size_t OFF_BIASM = OFF_WRSUM + (size_t)H * H;
static constexpr size_t OFF_INV_SM = OFF_BIASM + H;
static constexpr size_t OFF_INV_S  = OFF_INV_SM + NM;
static constexpr size_t OFF_INV_RM = OFF_INV_S + NS;
static constexpr size_t OFF_INV_R  = OFF_INV_RM + NM;
static constexpr size_t OFF_DVF    = OFF_INV_R + NR;
static constexpr size_t OFF_DVR    = OFF_DVF + NM;
static constexpr size_t TOTF       = OFF_DVR + NM;

__device__ float g_fbuf[TOTF];

static constexpr size_t IOFF_C_SM = 0;
static constexpr size_t IOFF_C_S  = IOFF_C_SM + NM;
static constexpr size_t IOFF_C_RM = IOFF_C_S + NS;
static constexpr size_t IOFF_C_R  = IOFF_C_RM + NM;
static constexpr size_t IOFF_C_DF = IOFF_C_R + NR;
static constexpr size_t IOFF_C_DR = IOFF_C_DF + NM;
static constexpr size_t TOTI      = IOFF_C_DR + NM;

__device__ int g_ibuf[TOTI];

// ---------------- helpers ----------------
__device__ __forceinline__ void red_add_v4(float* addr, float4 v) {
    asm volatile("red.global.add.v4.f32 [%0], {%1,%2,%3,%4};"
        :: "l"(addr), "f"(v.x), "f"(v.y), "f"(v.z), "f"(v.w) : "memory");
}

// ---------------- small kernels ----------------
__global__ void count_kernel(const int* __restrict__ idx, int* cnt, int E) {
    int i = blockIdx.x * blockDim.x + threadIdx.x;
    if (i < E) atomicAdd(&cnt[idx[i]], 1);
}

__global__ void make_inv_kernel(const int* __restrict__ cnt, float* inv, int n) {
    int i = blockIdx.x * blockDim.x + threadIdx.x;
    if (i < n) {
        float c = (float)cnt[i];
        inv[i] = 1.0f / fmaxf(c, 1.0f);
    }
}

__global__ void make_dinv_kernel(const int* __restrict__ cnt, float* dinv, int n) {
    int i = blockIdx.x * blockDim.x + threadIdx.x;
    if (i < n) {
        dinv[i] = rsqrtf((float)cnt[i] + 1.0f);  // +1 self loop; always > 0
    }
}

__global__ void add2_kernel(const float* __restrict__ a, const float* __restrict__ b,
                            float* o, int n) {
    int i = blockIdx.x * blockDim.x + threadIdx.x;
    if (i < n) o[i] = a[i] + b[i];
}

__global__ void add4_kernel(const float* __restrict__ a, const float* __restrict__ b,
                            const float* __restrict__ c, const float* __restrict__ d,
                            float* o, int n) {
    int i = blockIdx.x * blockDim.x + threadIdx.x;
    if (i < n) o[i] = a[i] + b[i] + c[i] + d[i];
}

// acc[i,:] = bias[:] + dvf[i]^2 * xw0[i,:] + dvr[i]^2 * xw1[i,:]   (GCN self loops + biases)
__global__ void acc_init_kernel(const float* __restrict__ xw0, const float* __restrict__ xw1,
                                const float* __restrict__ dvf, const float* __restrict__ dvr,
                                const float* __restrict__ bias, float* acc, int n) {
    int idx = blockIdx.x * blockDim.x + threadIdx.x;     // one float4 per thread
    int total = n * (H / 4);
    if (idx >= total) return;
    int i  = idx >> 5;            // / (H/4) == 32
    int j4 = (idx & 31) << 2;
    float f = dvf[i]; f *= f;
    float g = dvr[i]; g *= g;
    float4 a = *(const float4*)(xw0 + (size_t)i * H + j4);
    float4 b = *(const float4*)(xw1 + (size_t)i * H + j4);
    float4 bs = *(const float4*)(bias + j4);
    float4 o;
    o.x = bs.x + f * a.x + g * b.x;
    o.y = bs.y + f * a.y + g * b.y;
    o.z = bs.z + f * a.z + g * b.z;
    o.w = bs.w + f * a.w + g * b.w;
    *(float4*)(acc + (size_t)i * H + j4) = o;
}

// ---------------- edge scatter kernels (warp per edge) ----------------
__global__ void scatter_sage_kernel(const float* __restrict__ xsrc, float* agg,
                                    const int* __restrict__ src, const int* __restrict__ dst,
                                    int E) {
    int lane = threadIdx.x & 31;
    int warp = (blockIdx.x * blockDim.x + threadIdx.x) >> 5;
    int stride = (gridDim.x * blockDim.x) >> 5;
    for (int e = warp; e < E; e += stride) {
        int s = src[e], d = dst[e];
        float4 v = *(const float4*)(xsrc + (size_t)s * H + lane * 4);
        red_add_v4(agg + (size_t)d * H + lane * 4, v);
    }
}

// both GCN directions per edge
__global__ void scatter_gcn_kernel(const float* __restrict__ xw0, const float* __restrict__ xw1,
                                   const float* __restrict__ dvf, const float* __restrict__ dvr,
                                   float* acc,
                                   const int* __restrict__ src, const int* __restrict__ dst,
                                   int E) {
    int lane = threadIdx.x & 31;
    int warp = (blockIdx.x * blockDim.x + threadIdx.x) >> 5;
    int stride = (gridDim.x * blockDim.x) >> 5;
    for (int e = warp; e < E; e += stride) {
        int s = src[e], d = dst[e];
        float nf = dvf[s] * dvf[d];
        float nr = dvr[d] * dvr[s];
        float4 v0 = *(const float4*)(xw0 + (size_t)s * H + lane * 4);
        float4 v1 = *(const float4*)(xw1 + (size_t)d * H + lane * 4);
        v0.x *= nf; v0.y *= nf; v0.z *= nf; v0.w *= nf;
        v1.x *= nr; v1.y *= nr; v1.z *= nr; v1.w *= nr;
        red_add_v4(acc + (size_t)d * H + lane * 4, v0);
        red_add_v4(acc + (size_t)s * H + lane * 4, v1);
    }
}

// ---------------- fused multi-phase SGEMM: C = relu?( sum_p rowscale(A_p)@B_p + D + bias ) ----
#define APITCH 132
#define GEMM_SMEM ((128 + 128) * APITCH * 4)

__global__ void __launch_bounds__(256)
gemm_fused(int M, int np,
           const float* A0, const float* s0, const float* B0,
           const float* A1, const float* s1, const float* B1,
           const float* A2, const float* s2, const float* B2,
           const float* D, const float* bias, int do_relu, float* C) {
    extern __shared__ float smem[];
    float* As = smem;                     // [128][APITCH]  row-major [m][k]
    float* Bs = smem + 128 * APITCH;      // [128][APITCH]  row-major [k][n]
    int tid = threadIdx.x;
    int tx = tid & 15, ty = tid >> 4;
    int row0 = blockIdx.x * 128;

    float acc[8][8];
#pragma unroll
    for (int i = 0; i < 8; i++)
#pragma unroll
        for (int j = 0; j < 8; j++) acc[i][j] = 0.0f;

    for (int p = 0; p < np; p++) {
        const float *A, *Bw, *sc;
        if (p == 0)      { A = A0; Bw = B0; sc = s0; }
        else if (p == 1) { A = A1; Bw = B1; sc = s1; }
        else             { A = A2; Bw = B2; sc = s2; }

        __syncthreads();
        // load A tile 128x128 (row-scaled), coalesced
#pragma unroll
        for (int q = 0; q < 16; q++) {
            int lin = tid + q * 256;          // 0..4095 float4s
            int r   = lin >> 5;
            int k4  = (lin & 31) << 2;
            int grow = row0 + r;
            float4 v = make_float4(0.f, 0.f, 0.f, 0.f);
            if (grow < M) {
                v = *(const float4*)(A + (size_t)grow * H + k4);
                if (sc) {
                    float s = sc[grow];
                    v.x *= s; v.y *= s; v.z *= s; v.w *= s;
                }
            }
            *(float4*)(As + r * APITCH + k4) = v;
        }
        // load B 128x128
#pragma unroll
        for (int q = 0; q < 16; q++) {
            int lin = tid + q * 256;
            int r   = lin >> 5;
            int k4  = (lin & 31) << 2;
            *(float4*)(Bs + r * APITCH + k4) = *(const float4*)(Bw + (size_t)r * H + k4);
        }
        __syncthreads();

#pragma unroll 4
        for (int k = 0; k < H; k++) {
            float a[8], b[8];
#pragma unroll
            for (int i = 0; i < 4; i++) {
                a[i]     = As[(ty * 4 + i) * APITCH + k];
                a[4 + i] = As[(ty * 4 + 64 + i) * APITCH + k];
            }
            float4 b0 = *(const float4*)(Bs + k * APITCH + tx * 4);
            float4 b1 = *(const float4*)(Bs + k * APITCH + tx * 4 + 64);
            b[0] = b0.x; b[1] = b0.y; b[2] = b0.z; b[3] = b0.w;
            b[4] = b1.x; b[5] = b1.y; b[6] = b1.z; b[7] = b1.w;
#pragma unroll
            for (int i = 0; i < 8; i++)
#pragma unroll
                for (int j = 0; j < 8; j++)
                    acc[i][j] = fmaf(a[i], b[j], acc[i][j]);
        }
    }

    // epilogue
#pragma unroll
    for (int ih = 0; ih < 2; ih++) {
#pragma unroll
        for (int i = 0; i < 4; i++) {
            int r = row0 + ih * 64 + ty * 4 + i;
            if (r >= M) continue;
            int ia = ih * 4 + i;
#pragma unroll
            for (int jh = 0; jh < 2; jh++) {
                int c = jh * 64 + tx * 4;
                float4 v = make_float4(acc[ia][jh * 4 + 0], acc[ia][jh * 4 + 1],
                                       acc[ia][jh * 4 + 2], acc[ia][jh * 4 + 3]);
                if (D) {
                    float4 d = *(const float4*)(D + (size_t)r * H + c);
                    v.x += d.x; v.y += d.y; v.z += d.z; v.w += d.w;
                }
                if (bias) {
                    float4 bsv = *(const float4*)(bias + c);
                    v.x += bsv.x; v.y += bsv.y; v.z += bsv.z; v.w += bsv.w;
                }
                if (do_relu) {
                    v.x = fmaxf(v.x, 0.f); v.y = fmaxf(v.y, 0.f);
                    v.z = fmaxf(v.z, 0.f); v.w = fmaxf(v.w, 0.f);
                }
                *(float4*)(C + (size_t)r * H + c) = v;
            }
        }
    }
}

// ---------------- final link prediction ----------------
__global__ void predict_kernel(const float* __restrict__ xs, const float* __restrict__ xm,
                               const float* __restrict__ xr,
                               const int* __restrict__ ls, const int* __restrict__ lm,
                               const int* __restrict__ lr, float* out, int Ln) {
    int lane = threadIdx.x & 31;
    int warp = (blockIdx.x * blockDim.x + threadIdx.x) >> 5;
    if (warp >= Ln) return;
    int is = ls[warp], im = lm[warp], ir = lr[warp];
    float4 m = *(const float4*)(xm + (size_t)im * H + lane * 4);
    float4 s = *(const float4*)(xs + (size_t)is * H + lane * 4);
    float4 r = *(const float4*)(xr + (size_t)ir * H + lane * 4);
    float ds = s.x * m.x + s.y * m.y + s.z * m.z + s.w * m.w;
    float dr = r.x * m.x + r.y * m.y + r.z * m.z + r.w * m.w;
#pragma unroll
    for (int o = 16; o; o >>= 1) {
        ds += __shfl_xor_sync(0xffffffffu, ds, o);
        dr += __shfl_xor_sync(0xffffffffu, dr, o);
    }
    if (lane == 0) {
        out[warp] = ds;
        out[Ln + warp] = dr;
    }
}

// ---------------- host orchestration ----------------
static inline void gemm(int M, int np,
                        const float* A0, const float* s0, const float* B0,
                        const float* A1, const float* s1, const float* B1,
                        const float* A2, const float* s2, const float* B2,
                        const float* D, const float* bias, int relu, float* C) {
    gemm_fused<<<(M + 127) / 128, 256, GEMM_SMEM>>>(M, np, A0, s0, B0, A1, s1, B1,
                                                    A2, s2, B2, D, bias, relu, C);
}

extern "C" void kernel_launch(void* const* d_in, const int* in_sizes, int n_in,
                              void* d_out, int out_size) {
    (void)in_sizes; (void)n_in; (void)out_size;

    const float* emb_s = (const float*)d_in[0];
    const float* emb_m = (const float*)d_in[1];
    const float* emb_r = (const float*)d_in[2];
    const float* Wl    = (const float*)d_in[3];   // [2,4,H,H]
    const float* bl    = (const float*)d_in[4];   // [2,4,H]
    const float* Wr    = (const float*)d_in[5];   // [2,4,H,H]
    const float* Wg    = (const float*)d_in[6];   // [2,2,H,H]
    const float* bg    = (const float*)d_in[7];   // [2,2,H]
    const int* src_sm  = (const int*)d_in[8];
    const int* dst_sm  = (const int*)d_in[9];
    const int* src_rm  = (const int*)d_in[10];
    const int* dst_rm  = (const int*)d_in[11];
    const int* src_sim = (const int*)d_in[12];
    const int* dst_sim = (const int*)d_in[13];
    const int* lbl_s   = (const int*)d_in[14];
    const int* lbl_m   = (const int*)d_in[15];
    const int* lbl_r   = (const int*)d_in[16];
    float* out = (float*)d_out;

    float* fb = nullptr;
    int* ib = nullptr;
    cudaGetSymbolAddress((void**)&fb, g_fbuf);
    cudaGetSymbolAddress((void**)&ib, g_ibuf);

    float* xs[2]  = { fb + OFF_XS0, fb + OFF_XS1 };
    float* xm[2]  = { fb + OFF_XM0, fb + OFF_XM1 };
    float* xr[2]  = { fb + OFF_XR0, fb + OFF_XR1 };
    float* xw0    = fb + OFF_XW0;
    float* xw1    = fb + OFF_XW1;
    float* accm   = fb + OFF_ACCM;
    float* aggsm  = fb + OFF_AGGSM;
    float* aggrm  = fb + OFF_AGGRM;
    float* aggs   = fb + OFF_AGGS;
    float* aggr   = fb + OFF_AGGR;
    float* wrsum  = fb + OFF_WRSUM;
    float* biasm  = fb + OFF_BIASM;
    float* inv_sm = fb + OFF_INV_SM;
    float* inv_s  = fb + OFF_INV_S;
    float* inv_rm = fb + OFF_INV_RM;
    float* inv_r  = fb + OFF_INV_R;
    float* dvf    = fb + OFF_DVF;
    float* dvr    = fb + OFF_DVR;

    int* c_sm = ib + IOFF_C_SM;
    int* c_s  = ib + IOFF_C_S;
    int* c_rm = ib + IOFF_C_RM;
    int* c_r  = ib + IOFF_C_R;
    int* c_df = ib + IOFF_C_DF;
    int* c_dr = ib + IOFF_C_DR;

    cudaFuncSetAttribute(gemm_fused, cudaFuncAttributeMaxDynamicSharedMemorySize, GEMM_SMEM);

    const int TPB = 256;
    const int SCAT_BLOCKS = 2368;   // 148 SMs * 16

    // ---- degree / count precompute (edge-structure only; shared by both layers) ----
    cudaMemsetAsync(ib, 0, TOTI * sizeof(int));
    count_kernel<<<(E_SM + TPB - 1) / TPB, TPB>>>(dst_sm, c_sm, E_SM);
    count_kernel<<<(E_SM + TPB - 1) / TPB, TPB>>>(src_sm, c_s, E_SM);
    count_kernel<<<(E_RM + TPB - 1) / TPB, TPB>>>(dst_rm, c_rm, E_RM);
    count_kernel<<<(E_RM + TPB - 1) / TPB, TPB>>>(src_rm, c_r, E_RM);
    count_kernel<<<(E_SIM + TPB - 1) / TPB, TPB>>>(dst_sim, c_df, E_SIM);
    count_kernel<<<(E_SIM + TPB - 1) / TPB, TPB>>>(src_sim, c_dr, E_SIM);
    make_inv_kernel<<<(NM + TPB - 1) / TPB, TPB>>>(c_sm, inv_sm, NM);
    make_inv_kernel<<<(NS + TPB - 1) / TPB, TPB>>>(c_s, inv_s, NS);
    make_inv_kernel<<<(NM + TPB - 1) / TPB, TPB>>>(c_rm, inv_rm, NM);
    make_inv_kernel<<<(NR + TPB - 1) / TPB, TPB>>>(c_r, inv_r, NR);
    make_dinv_kernel<<<(NM + TPB - 1) / TPB, TPB>>>(c_df, dvf, NM);
    make_dinv_kernel<<<(NM + TPB - 1) / TPB, TPB>>>(c_dr, dvr, NM);

    const float* cxs = emb_s;
    const float* cxm = emb_m;
    const float* cxr = emb_r;

    for (int l = 0; l < 2; l++) {
        const float* Wl0 = Wl + (size_t)(l * 4 + 0) * H * H;
        const float* Wl1 = Wl + (size_t)(l * 4 + 1) * H * H;
        const float* Wl2 = Wl + (size_t)(l * 4 + 2) * H * H;
        const float* Wl3 = Wl + (size_t)(l * 4 + 3) * H * H;
        const float* Wr0 = Wr + (size_t)(l * 4 + 0) * H * H;
        const float* Wr1 = Wr + (size_t)(l * 4 + 1) * H * H;
        const float* Wr2 = Wr + (size_t)(l * 4 + 2) * H * H;
        const float* Wr3 = Wr + (size_t)(l * 4 + 3) * H * H;
        const float* bl0 = bl + (size_t)(l * 4 + 0) * H;
        const float* bl1 = bl + (size_t)(l * 4 + 1) * H;
        const float* bl2 = bl + (size_t)(l * 4 + 2) * H;
        const float* bl3 = bl + (size_t)(l * 4 + 3) * H;
        const float* Wg0 = Wg + (size_t)(l * 2 + 0) * H * H;
        const float* Wg1 = Wg + (size_t)(l * 2 + 1) * H * H;
        const float* bg0 = bg + (size_t)(l * 2 + 0) * H;
        const float* bg1 = bg + (size_t)(l * 2 + 1) * H;

        // GCN transforms
        gemm(NM, 1, cxm, nullptr, Wg0, nullptr, nullptr, nullptr,
             nullptr, nullptr, nullptr, nullptr, nullptr, 0, xw0);
        gemm(NM, 1, cxm, nullptr, Wg1, nullptr, nullptr, nullptr,
             nullptr, nullptr, nullptr, nullptr, nullptr, 0, xw1);

        // combined bias + Wr0+Wr2
        add4_kernel<<<1, H>>>(bl0, bl2, bg0, bg1, biasm, H);
        add2_kernel<<<(H * H + TPB - 1) / TPB, TPB>>>(Wr0, Wr2, wrsum, H * H);

        // GCN self loops + bias into accumulator, then scatter both GCN directions
        acc_init_kernel<<<(NM * (H / 4) + TPB - 1) / TPB, TPB>>>(xw0, xw1, dvf, dvr,
                                                                 biasm, accm, NM);
        scatter_gcn_kernel<<<SCAT_BLOCKS, TPB>>>(xw0, xw1, dvf, dvr, accm,
                                                 src_sim, dst_sim, E_SIM);

        // SAGE aggregations
        cudaMemsetAsync(aggsm, 0, SZ_M * sizeof(float));
        cudaMemsetAsync(aggrm, 0, SZ_M * sizeof(float));
        cudaMemsetAsync(aggs, 0, SZ_S * sizeof(float));
        cudaMemsetAsync(aggr, 0, SZ_R * sizeof(float));
        scatter_sage_kernel<<<SCAT_BLOCKS, TPB>>>(cxs, aggsm, src_sm, dst_sm, E_SM);
        scatter_sage_kernel<<<SCAT_BLOCKS, TPB>>>(cxr, aggrm, src_rm, dst_rm, E_RM);
        scatter_sage_kernel<<<SCAT_BLOCKS, TPB>>>(cxm, aggs, dst_sm, src_sm, E_SM);
        scatter_sage_kernel<<<SCAT_BLOCKS, TPB>>>(cxm, aggr, dst_rm, src_rm, E_RM);

        // fused output GEMMs (+ ReLU)
        gemm(NM, 3, aggsm, inv_sm, Wl0, aggrm, inv_rm, Wl2, cxm, nullptr, wrsum,
             accm, nullptr, 1, xm[l]);
        gemm(NS, 2, aggs, inv_s, Wl1, cxs, nullptr, Wr1, nullptr, nullptr, nullptr,
             nullptr, bl1, 1, xs[l]);
        gemm(NR, 2, aggr, inv_r, Wl3, cxr, nullptr, Wr3, nullptr, nullptr, nullptr,
             nullptr, bl3, 1, xr[l]);

        cxs = xs[l]; cxm = xm[l]; cxr = xr[l];
    }

    predict_kernel<<<(NLBL * 32 + TPB - 1) / TPB, TPB>>>(cxs, cxm, cxr,
                                                         lbl_s, lbl_m, lbl_r, out, NLBL);
}

// round 9
// speedup vs baseline: 1.4038x; 1.4038x over previous
#include <cuda_runtime.h>
#include <cstdint>

#define NS 5000
#define NM 100000
#define NR 2000
#define H  128
#define E_SM  2000000
#define E_RM  1000000
#define E_SIM 2000000
#define NLBL  500000

// ---------------- static device scratch (no cudaMalloc allowed) ----------------
static constexpr size_t SZ_S = (size_t)NS * H;
static constexpr size_t SZ_M = (size_t)NM * H;
static constexpr size_t SZ_R = (size_t)NR * H;

static constexpr size_t OFF_XS0   = 0;
static constexpr size_t OFF_XS1   = OFF_XS0 + SZ_S;
static constexpr size_t OFF_XR0   = OFF_XS1 + SZ_S;
static constexpr size_t OFF_XR1   = OFF_XR0 + SZ_R;
static constexpr size_t OFF_AGGS  = OFF_XR1 + SZ_R;
static constexpr size_t OFF_AGGR  = OFF_AGGS + SZ_S;
static constexpr size_t OFF_XM0   = OFF_AGGR + SZ_R;
static constexpr size_t OFF_XM1   = OFF_XM0 + SZ_M;
static constexpr size_t OFF_XW0   = OFF_XM1 + SZ_M;
static constexpr size_t OFF_XW1   = OFF_XW0 + SZ_M;
static constexpr size_t OFF_ACCM  = OFF_XW1 + SZ_M;
static constexpr size_t OFF_AGGSM = OFF_ACCM + SZ_M;
static constexpr size_t OFF_AGGRM = OFF_AGGSM + SZ_M;
static constexpr size_t OFF_WRSUM = OFF_AGGRM + SZ_M;
static constexpr size_t OFF_BIASM = OFF_WRSUM + (size_t)H * H;
static constexpr size_t OFF_DVF   = OFF_BIASM + H;
static constexpr size_t OFF_DVR   = OFF_DVF + NM;
static constexpr size_t TOTF      = OFF_DVR + NM;

__device__ float g_fbuf[TOTF];

// ---- int scratch: counts, CSR offsets, cursors, payloads ----
static constexpr size_t C_SMD  = 0;
static constexpr size_t C_SMS  = C_SMD + NM;
static constexpr size_t C_RMD  = C_SMS + NS;
static constexpr size_t C_RMS  = C_RMD + NM;
static constexpr size_t C_SIMD = C_RMS + NR;
static constexpr size_t C_SIMS = C_SIMD + NM;
static constexpr size_t CNT_TOT = C_SIMS + NM;

static constexpr size_t O_SMD  = 0;
static constexpr size_t O_SMS  = O_SMD + NM + 1;
static constexpr size_t O_RMD  = O_SMS + NS + 1;
static constexpr size_t O_RMS  = O_RMD + NM + 1;
static constexpr size_t O_SIMD = O_RMS + NR + 1;
static constexpr size_t O_SIMS = O_SIMD + NM + 1;
static constexpr size_t OFF_TOT = O_SIMS + NM + 1;

static constexpr size_t P_SMD  = 0;
static constexpr size_t P_SMS  = P_SMD + E_SM;
static constexpr size_t P_RMD  = P_SMS + E_SM;
static constexpr size_t P_RMS  = P_RMD + E_RM;
static constexpr size_t P_SIMD = P_RMS + E_RM;
static constexpr size_t P_SIMS = P_SIMD + E_SIM;
static constexpr size_t PAY_TOT = P_SIMS + E_SIM;

static constexpr size_t IOFF_CNT = 0;
static constexpr size_t IOFF_OFF = IOFF_CNT + CNT_TOT;
static constexpr size_t IOFF_CUR = IOFF_OFF + OFF_TOT;
static constexpr size_t IOFF_PAY = IOFF_CUR + OFF_TOT;
static constexpr size_t TOTI     = IOFF_PAY + PAY_TOT;

__device__ int g_ibuf[TOTI];

// ---------------- CSR build ----------------
__global__ void count6_kernel(const int* __restrict__ src_sm, const int* __restrict__ dst_sm,
                              const int* __restrict__ src_rm, const int* __restrict__ dst_rm,
                              const int* __restrict__ src_sim, const int* __restrict__ dst_sim,
                              int* cnt) {
    int i = blockIdx.x * blockDim.x + threadIdx.x;
    if (i < E_SM) {
        atomicAdd(cnt + C_SMD + dst_sm[i], 1);
        atomicAdd(cnt + C_SMS + src_sm[i], 1);
    }
    if (i < E_RM) {
        atomicAdd(cnt + C_RMD + dst_rm[i], 1);
        atomicAdd(cnt + C_RMS + src_rm[i], 1);
    }
    if (i < E_SIM) {
        atomicAdd(cnt + C_SIMD + dst_sim[i], 1);
        atomicAdd(cnt + C_SIMS + src_sim[i], 1);
    }
}

// 6 blocks, one exclusive scan each
__global__ void scan6_kernel(int* ib) {
    __shared__ int sums[1024];
    const size_t c_ofs[6] = { C_SMD, C_SMS, C_RMD, C_RMS, C_SIMD, C_SIMS };
    const size_t o_ofs[6] = { O_SMD, O_SMS, O_RMD, O_RMS, O_SIMD, O_SIMS };
    const int    ns[6]    = { NM, NS, NM, NR, NM, NM };
    int b = blockIdx.x;
    const int* cnt = ib + IOFF_CNT + c_ofs[b];
    int* off = ib + IOFF_OFF + o_ofs[b];
    int n = ns[b];
    int t = threadIdx.x;
    int chunk = (n + 1023) >> 10;
    int lo = t * chunk, hi = min(lo + chunk, n);
    int s = 0;
    for (int i = lo; i < hi; i++) s += cnt[i];
    sums[t] = s;
    __syncthreads();
    for (int d = 1; d < 1024; d <<= 1) {
        int v = (t >= d) ? sums[t - d] : 0;
        __syncthreads();
        sums[t] += v;
        __syncthreads();
    }
    int run = (t == 0) ? 0 : sums[t - 1];
    for (int i = lo; i < hi; i++) { off[i] = run; run += cnt[i]; }
    if (t == 1023) off[n] = sums[1023];
}

__global__ void fill6_kernel(const int* __restrict__ src_sm, const int* __restrict__ dst_sm,
                             const int* __restrict__ src_rm, const int* __restrict__ dst_rm,
                             const int* __restrict__ src_sim, const int* __restrict__ dst_sim,
                             int* cur, int* pay) {
    int i = blockIdx.x * blockDim.x + threadIdx.x;
    if (i < E_SM) {
        int s = src_sm[i], d = dst_sm[i];
        pay[P_SMD + atomicAdd(cur + O_SMD + d, 1)] = s;
        pay[P_SMS + atomicAdd(cur + O_SMS + s, 1)] = d;
    }
    if (i < E_RM) {
        int s = src_rm[i], d = dst_rm[i];
        pay[P_RMD + atomicAdd(cur + O_RMD + d, 1)] = s;
        pay[P_RMS + atomicAdd(cur + O_RMS + s, 1)] = d;
    }
    if (i < E_SIM) {
        int s = src_sim[i], d = dst_sim[i];
        pay[P_SIMD + atomicAdd(cur + O_SIMD + d, 1)] = s;
        pay[P_SIMS + atomicAdd(cur + O_SIMS + s, 1)] = d;
    }
}

__global__ void make_dv_kernel(const int* __restrict__ off_d, const int* __restrict__ off_s,
                               float* dvf, float* dvr, int n) {
    int i = blockIdx.x * blockDim.x + threadIdx.x;
    if (i < n) {
        dvf[i] = rsqrtf((float)(off_d[i + 1] - off_d[i] + 1));
        dvr[i] = rsqrtf((float)(off_s[i + 1] - off_s[i] + 1));
    }
}

// ---------------- small elementwise ----------------
__global__ void add2_kernel(const float* __restrict__ a, const float* __restrict__ b,
                            float* o, int n) {
    int i = blockIdx.x * blockDim.x + threadIdx.x;
    if (i < n) o[i] = a[i] + b[i];
}

__global__ void add4_kernel(const float* __restrict__ a, const float* __restrict__ b,
                            const float* __restrict__ c, const float* __restrict__ d,
                            float* o, int n) {
    int i = blockIdx.x * blockDim.x + threadIdx.x;
    if (i < n) o[i] = a[i] + b[i] + c[i] + d[i];
}

// ---------------- gather-reduce kernels (warp per node) ----------------
__device__ __forceinline__ void acc4(float4& a, const float4 v) {
    a.x += v.x; a.y += v.y; a.z += v.z; a.w += v.w;
}
__device__ __forceinline__ void fma4(float4& a, float w, const float4 v) {
    a.x = fmaf(w, v.x, a.x); a.y = fmaf(w, v.y, a.y);
    a.z = fmaf(w, v.z, a.z); a.w = fmaf(w, v.w, a.w);
}

__device__ __forceinline__ float4 mean_gather(const float* __restrict__ x,
                                              const int* __restrict__ pay,
                                              int lo, int hi, int c) {
    float4 a = make_float4(0.f, 0.f, 0.f, 0.f);
    int j = lo;
    for (; j + 1 < hi; j += 2) {
        int s0 = __ldg(&pay[j]);
        int s1 = __ldg(&pay[j + 1]);
        float4 v0 = *(const float4*)(x + (size_t)s0 * H + c);
        float4 v1 = *(const float4*)(x + (size_t)s1 * H + c);
        acc4(a, v0); acc4(a, v1);
    }
    if (j < hi) {
        int s0 = __ldg(&pay[j]);
        acc4(a, *(const float4*)(x + (size_t)s0 * H + c));
    }
    float sc = 1.0f / fmaxf((float)(hi - lo), 1.0f);
    a.x *= sc; a.y *= sc; a.z *= sc; a.w *= sc;
    return a;
}

// fused m-side aggregation: SAGE(s->m), SAGE(r->m), GCN both directions (+self loops)
__global__ void __launch_bounds__(256)
m_gather_kernel(const float* __restrict__ xs, const float* __restrict__ xr,
                const float* __restrict__ xw0, const float* __restrict__ xw1,
                const float* __restrict__ dvf, const float* __restrict__ dvr,
                const int* __restrict__ ib_off, const int* __restrict__ ib_pay,
                float* aggsm, float* aggrm, float* accm) {
    int node = (blockIdx.x * blockDim.x + threadIdx.x) >> 5;
    int lane = threadIdx.x & 31;
    if (node >= NM) return;
    int c = lane * 4;
    size_t rowoff = (size_t)node * H + c;

    // SAGE s->m
    {
        int lo = __ldg(&ib_off[O_SMD + node]), hi = __ldg(&ib_off[O_SMD + node + 1]);
        float4 a = mean_gather(xs, ib_pay + P_SMD, lo, hi, c);
        *(float4*)(aggsm + rowoff) = a;
    }
    // SAGE r->m
    {
        int lo = __ldg(&ib_off[O_RMD + node]), hi = __ldg(&ib_off[O_RMD + node + 1]);
        float4 a = mean_gather(xr, ib_pay + P_RMD, lo, hi, c);
        *(float4*)(aggrm + rowoff) = a;
    }
    // GCN forward + reverse (+ self loops)
    {
        float df = __ldg(&dvf[node]);
        float dr = __ldg(&dvr[node]);
        float4 g = make_float4(0.f, 0.f, 0.f, 0.f);
        float4 v0 = *(const float4*)(xw0 + rowoff);
        float4 v1 = *(const float4*)(xw1 + rowoff);
        fma4(g, df * df, v0);
        fma4(g, dr * dr, v1);
        int lo = __ldg(&ib_off[O_SIMD + node]), hi = __ldg(&ib_off[O_SIMD + node + 1]);
        const int* pf = ib_pay + P_SIMD;
        int j = lo;
        for (; j + 1 < hi; j += 2) {
            int s0 = __ldg(&pf[j]);
            int s1 = __ldg(&pf[j + 1]);
            float w0 = df * __ldg(&dvf[s0]);
            float w1 = df * __ldg(&dvf[s1]);
            float4 a0 = *(const float4*)(xw0 + (size_t)s0 * H + c);
            float4 a1 = *(const float4*)(xw0 + (size_t)s1 * H + c);
            fma4(g, w0, a0); fma4(g, w1, a1);
        }
        if (j < hi) {
            int s0 = __ldg(&pf[j]);
            fma4(g, df * __ldg(&dvf[s0]), *(const float4*)(xw0 + (size_t)s0 * H + c));
        }
        lo = __ldg(&ib_off[O_SIMS + node]); hi = __ldg(&ib_off[O_SIMS + node + 1]);
        const int* pr = ib_pay + P_SIMS;
        j = lo;
        for (; j + 1 < hi; j += 2) {
            int t0 = __ldg(&pr[j]);
            int t1 = __ldg(&pr[j + 1]);
            float w0 = dr * __ldg(&dvr[t0]);
            float w1 = dr * __ldg(&dvr[t1]);
            float4 a0 = *(const float4*)(xw1 + (size_t)t0 * H + c);
            float4 a1 = *(const float4*)(xw1 + (size_t)t1 * H + c);
            fma4(g, w0, a0); fma4(g, w1, a1);
        }
        if (j < hi) {
            int t0 = __ldg(&pr[j]);
            fma4(g, dr * __ldg(&dvr[t0]), *(const float4*)(xw1 + (size_t)t0 * H + c));
        }
        *(float4*)(accm + rowoff) = g;
    }
}

// generic mean gather (for s and r sides; source = x_m)
__global__ void __launch_bounds__(256)
gather_mean_kernel(const float* __restrict__ xsrc, const int* __restrict__ off,
                   const int* __restrict__ pay, float* out, int n) {
    int node = (blockIdx.x * blockDim.x + threadIdx.x) >> 5;
    int lane = threadIdx.x & 31;
    if (node >= n) return;
    int c = lane * 4;
    int lo = __ldg(&off[node]), hi = __ldg(&off[node + 1]);
    float4 a = mean_gather(xsrc, pay, lo, hi, c);
    *(float4*)(out + (size_t)node * H + c) = a;
}

// ---------------- fused multi-phase SGEMM: C = relu?( sum_p A_p@B_p + D + bias ) ----
#define APITCH 132
#define GEMM_SMEM ((128 + 128) * APITCH * 4)

__global__ void __launch_bounds__(256)
gemm_fused(int M, int np,
           const float* A0, const float* B0,
           const float* A1, const float* B1,
           const float* A2, const float* B2,
           const float* D, const float* bias, int do_relu, float* C) {
    extern __shared__ float smem[];
    float* As = smem;                     // [128][APITCH]  row-major [m][k]
    float* Bs = smem + 128 * APITCH;      // [128][APITCH]  row-major [k][n]
    int tid = threadIdx.x;
    int tx = tid & 15, ty = tid >> 4;
    int row0 = blockIdx.x * 128;

    float acc[8][8];
#pragma unroll
    for (int i = 0; i < 8; i++)
#pragma unroll
        for (int j = 0; j < 8; j++) acc[i][j] = 0.0f;

    for (int p = 0; p < np; p++) {
        const float *A, *Bw;
        if (p == 0)      { A = A0; Bw = B0; }
        else if (p == 1) { A = A1; Bw = B1; }
        else             { A = A2; Bw = B2; }

        __syncthreads();
#pragma unroll
        for (int q = 0; q < 16; q++) {
            int lin = tid + q * 256;
            int r   = lin >> 5;
            int k4  = (lin & 31) << 2;
            int grow = row0 + r;
            float4 v = make_float4(0.f, 0.f, 0.f, 0.f);
            if (grow < M) v = *(const float4*)(A + (size_t)grow * H + k4);
            *(float4*)(As + r * APITCH + k4) = v;
        }
#pragma unroll
        for (int q = 0; q < 16; q++) {
            int lin = tid + q * 256;
            int r   = lin >> 5;
            int k4  = (lin & 31) << 2;
            *(float4*)(Bs + r * APITCH + k4) = *(const float4*)(Bw + (size_t)r * H + k4);
        }
        __syncthreads();

#pragma unroll 4
        for (int k = 0; k < H; k++) {
            float a[8], b[8];
#pragma unroll
            for (int i = 0; i < 4; i++) {
                a[i]     = As[(ty * 4 + i) * APITCH + k];
                a[4 + i] = As[(ty * 4 + 64 + i) * APITCH + k];
            }
            float4 b0 = *(const float4*)(Bs + k * APITCH + tx * 4);
            float4 b1 = *(const float4*)(Bs + k * APITCH + tx * 4 + 64);
            b[0] = b0.x; b[1] = b0.y; b[2] = b0.z; b[3] = b0.w;
            b[4] = b1.x; b[5] = b1.y; b[6] = b1.z; b[7] = b1.w;
#pragma unroll
            for (int i = 0; i < 8; i++)
#pragma unroll
                for (int j = 0; j < 8; j++)
                    acc[i][j] = fmaf(a[i], b[j], acc[i][j]);
        }
    }

#pragma unroll
    for (int ih = 0; ih < 2; ih++) {
#pragma unroll
        for (int i = 0; i < 4; i++) {
            int r = row0 + ih * 64 + ty * 4 + i;
            if (r >= M) continue;
            int ia = ih * 4 + i;
#pragma unroll
            for (int jh = 0; jh < 2; jh++) {
                int cc = jh * 64 + tx * 4;
                float4 v = make_float4(acc[ia][jh * 4 + 0], acc[ia][jh * 4 + 1],
                                       acc[ia][jh * 4 + 2], acc[ia][jh * 4 + 3]);
                if (D) {
                    float4 d = *(const float4*)(D + (size_t)r * H + cc);
                    v.x += d.x; v.y += d.y; v.z += d.z; v.w += d.w;
                }
                if (bias) {
                    float4 bsv = *(const float4*)(bias + cc);
                    v.x += bsv.x; v.y += bsv.y; v.z += bsv.z; v.w += bsv.w;
                }
                if (do_relu) {
                    v.x = fmaxf(v.x, 0.f); v.y = fmaxf(v.y, 0.f);
                    v.z = fmaxf(v.z, 0.f); v.w = fmaxf(v.w, 0.f);
                }
                *(float4*)(C + (size_t)r * H + cc) = v;
            }
        }
    }
}

// ---------------- final link prediction ----------------
__global__ void predict_kernel(const float* __restrict__ xs, const float* __restrict__ xm,
                               const float* __restrict__ xr,
                               const int* __restrict__ ls, const int* __restrict__ lm,
                               const int* __restrict__ lr, float* out, int Ln) {
    int lane = threadIdx.x & 31;
    int warp = (blockIdx.x * blockDim.x + threadIdx.x) >> 5;
    if (warp >= Ln) return;
    int is = ls[warp], im = lm[warp], ir = lr[warp];
    float4 m = *(const float4*)(xm + (size_t)im * H + lane * 4);
    float4 s = *(const float4*)(xs + (size_t)is * H + lane * 4);
    float4 r = *(const float4*)(xr + (size_t)ir * H + lane * 4);
    float ds = s.x * m.x + s.y * m.y + s.z * m.z + s.w * m.w;
    float dr = r.x * m.x + r.y * m.y + r.z * m.z + r.w * m.w;
#pragma unroll
    for (int o = 16; o; o >>= 1) {
        ds += __shfl_xor_sync(0xffffffffu, ds, o);
        dr += __shfl_xor_sync(0xffffffffu, dr, o);
    }
    if (lane == 0) {
        out[warp] = ds;
        out[Ln + warp] = dr;
    }
}

// ---------------- host orchestration ----------------
static inline void gemm(int M, int np,
                        const float* A0, const float* B0,
                        const float* A1, const float* B1,
                        const float* A2, const float* B2,
                        const float* D, const float* bias, int relu, float* C) {
    gemm_fused<<<(M + 127) / 128, 256, GEMM_SMEM>>>(M, np, A0, B0, A1, B1, A2, B2,
                                                    D, bias, relu, C);
}

extern "C" void kernel_launch(void* const* d_in, const int* in_sizes, int n_in,
                              void* d_out, int out_size) {
    (void)in_sizes; (void)n_in; (void)out_size;

    const float* emb_s = (const float*)d_in[0];
    const float* emb_m = (const float*)d_in[1];
    const float* emb_r = (const float*)d_in[2];
    const float* Wl    = (const float*)d_in[3];   // [2,4,H,H]
    const float* bl    = (const float*)d_in[4];   // [2,4,H]
    const float* Wr    = (const float*)d_in[5];   // [2,4,H,H]
    const float* Wg    = (const float*)d_in[6];   // [2,2,H,H]
    const float* bg    = (const float*)d_in[7];   // [2,2,H]
    const int* src_sm  = (const int*)d_in[8];
    const int* dst_sm  = (const int*)d_in[9];
    const int* src_rm  = (const int*)d_in[10];
    const int* dst_rm  = (const int*)d_in[11];
    const int* src_sim = (const int*)d_in[12];
    const int* dst_sim = (const int*)d_in[13];
    const int* lbl_s   = (const int*)d_in[14];
    const int* lbl_m   = (const int*)d_in[15];
    const int* lbl_r   = (const int*)d_in[16];
    float* out = (float*)d_out;

    float* fb = nullptr;
    int* ib = nullptr;
    cudaGetSymbolAddress((void**)&fb, g_fbuf);
    cudaGetSymbolAddress((void**)&ib, g_ibuf);

    float* xs[2]  = { fb + OFF_XS0, fb + OFF_XS1 };
    float* xm[2]  = { fb + OFF_XM0, fb + OFF_XM1 };
    float* xr[2]  = { fb + OFF_XR0, fb + OFF_XR1 };
    float* xw0    = fb + OFF_XW0;
    float* xw1    = fb + OFF_XW1;
    float* accm   = fb + OFF_ACCM;
    float* aggsm  = fb + OFF_AGGSM;
    float* aggrm  = fb + OFF_AGGRM;
    float* aggs   = fb + OFF_AGGS;
    float* aggr   = fb + OFF_AGGR;
    float* wrsum  = fb + OFF_WRSUM;
    float* biasm  = fb + OFF_BIASM;
    float* dvf    = fb + OFF_DVF;
    float* dvr    = fb + OFF_DVR;

    int* ib_cnt = ib + IOFF_CNT;
    int* ib_off = ib + IOFF_OFF;
    int* ib_cur = ib + IOFF_CUR;
    int* ib_pay = ib + IOFF_PAY;

    cudaFuncSetAttribute(gemm_fused, cudaFuncAttributeMaxDynamicSharedMemorySize, GEMM_SMEM);

    const int TPB = 256;

    // ---- CSR build (edge structure only; reused by both layers) ----
    cudaMemsetAsync(ib_cnt, 0, CNT_TOT * sizeof(int));
    count6_kernel<<<(E_SM + TPB - 1) / TPB, TPB>>>(src_sm, dst_sm, src_rm, dst_rm,
                                                   src_sim, dst_sim, ib_cnt);
    scan6_kernel<<<6, 1024>>>(ib);
    cudaMemcpyAsync(ib_cur, ib_off, OFF_TOT * sizeof(int), cudaMemcpyDeviceToDevice);
    fill6_kernel<<<(E_SM + TPB - 1) / TPB, TPB>>>(src_sm, dst_sm, src_rm, dst_rm,
                                                  src_sim, dst_sim, ib_cur, ib_pay);
    make_dv_kernel<<<(NM + TPB - 1) / TPB, TPB>>>(ib_off + O_SIMD, ib_off + O_SIMS,
                                                  dvf, dvr, NM);

    const float* cxs = emb_s;
    const float* cxm = emb_m;
    const float* cxr = emb_r;

    for (int l = 0; l < 2; l++) {
        const float* Wl0 = Wl + (size_t)(l * 4 + 0) * H * H;
        const float* Wl1 = Wl + (size_t)(l * 4 + 1) * H * H;
        const float* Wl2 = Wl + (size_t)(l * 4 + 2) * H * H;
        const float* Wl3 = Wl + (size_t)(l * 4 + 3) * H * H;
        const float* Wr0 = Wr + (size_t)(l * 4 + 0) * H * H;
        const float* Wr1 = Wr + (size_t)(l * 4 + 1) * H * H;
        const float* Wr2 = Wr + (size_t)(l * 4 + 2) * H * H;
        const float* Wr3 = Wr + (size_t)(l * 4 + 3) * H * H;
        const float* bl0 = bl + (size_t)(l * 4 + 0) * H;
        const float* bl1 = bl + (size_t)(l * 4 + 1) * H;
        const float* bl2 = bl + (size_t)(l * 4 + 2) * H;
        const float* bl3 = bl + (size_t)(l * 4 + 3) * H;
        const float* Wg0 = Wg + (size_t)(l * 2 + 0) * H * H;
        const float* Wg1 = Wg + (size_t)(l * 2 + 1) * H * H;
        const float* bg0 = bg + (size_t)(l * 2 + 0) * H;
        const float* bg1 = bg + (size_t)(l * 2 + 1) * H;

        // GCN transforms
        gemm(NM, 1, cxm, Wg0, nullptr, nullptr, nullptr, nullptr,
             nullptr, nullptr, 0, xw0);
        gemm(NM, 1, cxm, Wg1, nullptr, nullptr, nullptr, nullptr,
             nullptr, nullptr, 0, xw1);

        // combined bias (bl0+bl2+bg0+bg1) and Wr0+Wr2
        add4_kernel<<<1, H>>>(bl0, bl2, bg0, bg1, biasm, H);
        add2_kernel<<<(H * H + TPB - 1) / TPB, TPB>>>(Wr0, Wr2, wrsum, H * H);

        // fused m-side aggregation (SAGE s->m, SAGE r->m, GCN both dirs + self loops)
        m_gather_kernel<<<(NM * 32 + TPB - 1) / TPB, TPB>>>(cxs, cxr, xw0, xw1, dvf, dvr,
                                                            ib_off, ib_pay,
                                                            aggsm, aggrm, accm);
        // s- and r-side SAGE aggregations (gather from x_m)
        gather_mean_kernel<<<(NS * 32 + TPB - 1) / TPB, TPB>>>(cxm, ib_off + O_SMS,
                                                               ib_pay + P_SMS, aggs, NS);
        gather_mean_kernel<<<(NR * 32 + TPB - 1) / TPB, TPB>>>(cxm, ib_off + O_RMS,
                                                               ib_pay + P_RMS, aggr, NR);

        // fused output GEMMs (+ ReLU)
        gemm(NM, 3, aggsm, Wl0, aggrm, Wl2, cxm, wrsum, accm, biasm, 1, xm[l]);
        gemm(NS, 2, aggs, Wl1, cxs, Wr1, nullptr, nullptr, nullptr, bl1, 1, xs[l]);
        gemm(NR, 2, aggr, Wl3, cxr, Wr3, nullptr, nullptr, nullptr, bl3, 1, xr[l]);

        cxs = xs[l]; cxm = xm[l]; cxr = xr[l];
    }

    predict_kernel<<<(NLBL * 32 + TPB - 1) / TPB, TPB>>>(cxs, cxm, cxr,
                                                         lbl_s, lbl_m, lbl_r, out, NLBL);
}

// round 11
// speedup vs baseline: 1.4866x; 1.0590x over previous
#include <cuda_runtime.h>
#include <cstdint>

#define NS 5000
#define NM 100000
#define NR 2000
#define H  128
#define E_SM  2000000
#define E_RM  1000000
#define E_SIM 2000000
#define NLBL  500000

// ---------------- static device scratch (no cudaMalloc allowed) ----------------
static constexpr size_t SZ_S = (size_t)NS * H;
static constexpr size_t SZ_M = (size_t)NM * H;
static constexpr size_t SZ_R = (size_t)NR * H;

static constexpr size_t OFF_XS0   = 0;
static constexpr size_t OFF_XS1   = OFF_XS0 + SZ_S;
static constexpr size_t OFF_XR0   = OFF_XS1 + SZ_S;
static constexpr size_t OFF_XR1   = OFF_XR0 + SZ_R;
static constexpr size_t OFF_AGGS  = OFF_XR1 + SZ_R;
static constexpr size_t OFF_AGGR  = OFF_AGGS + SZ_S;
static constexpr size_t OFF_XM0   = OFF_AGGR + SZ_R;
static constexpr size_t OFF_XM1   = OFF_XM0 + SZ_M;
static constexpr size_t OFF_XW0   = OFF_XM1 + SZ_M;
static constexpr size_t OFF_XW1   = OFF_XW0 + SZ_M;
static constexpr size_t OFF_ACCM  = OFF_XW1 + SZ_M;
static constexpr size_t OFF_AGGSM = OFF_ACCM + SZ_M;
static constexpr size_t OFF_AGGRM = OFF_AGGSM + SZ_M;
static constexpr size_t OFF_WRSUM = OFF_AGGRM + SZ_M;
static constexpr size_t OFF_BIASM = OFF_WRSUM + (size_t)H * H;
static constexpr size_t OFF_DVF   = OFF_BIASM + H;
static constexpr size_t OFF_DVR   = OFF_DVF + NM;
static constexpr size_t TOTF      = OFF_DVR + NM;

__device__ float g_fbuf[TOTF];

// ---- int scratch: counts, CSR offsets, cursors, payloads ----
static constexpr size_t C_SMD  = 0;
static constexpr size_t C_SMS  = C_SMD + NM;
static constexpr size_t C_RMD  = C_SMS + NS;
static constexpr size_t C_RMS  = C_RMD + NM;
static constexpr size_t C_SIMD = C_RMS + NR;
static constexpr size_t C_SIMS = C_SIMD + NM;
static constexpr size_t CNT_TOT = C_SIMS + NM;

static constexpr size_t O_SMD  = 0;
static constexpr size_t O_SMS  = O_SMD + NM + 1;
static constexpr size_t O_RMD  = O_SMS + NS + 1;
static constexpr size_t O_RMS  = O_RMD + NM + 1;
static constexpr size_t O_SIMD = O_RMS + NR + 1;
static constexpr size_t O_SIMS = O_SIMD + NM + 1;
static constexpr size_t OFF_TOT = O_SIMS + NM + 1;

static constexpr size_t P_SMD  = 0;
static constexpr size_t P_SMS  = P_SMD + E_SM;
static constexpr size_t P_RMD  = P_SMS + E_SM;
static constexpr size_t P_RMS  = P_RMD + E_RM;
static constexpr size_t P_SIMD = P_RMS + E_RM;
static constexpr size_t P_SIMS = P_SIMD + E_SIM;
static constexpr size_t PAY_TOT = P_SIMS + E_SIM;

static constexpr size_t IOFF_CNT = 0;
static constexpr size_t IOFF_OFF = IOFF_CNT + CNT_TOT;
static constexpr size_t IOFF_CUR = IOFF_OFF + OFF_TOT;
static constexpr size_t IOFF_PAY = IOFF_CUR + OFF_TOT;
static constexpr size_t TOTI     = IOFF_PAY + PAY_TOT;

__device__ int g_ibuf[TOTI];

// ---------------- CSR build ----------------
__global__ void count6_kernel(const int* __restrict__ src_sm, const int* __restrict__ dst_sm,
                              const int* __restrict__ src_rm, const int* __restrict__ dst_rm,
                              const int* __restrict__ src_sim, const int* __restrict__ dst_sim,
                              int* cnt) {
    int i = blockIdx.x * blockDim.x + threadIdx.x;
    if (i < E_SM) {
        atomicAdd(cnt + C_SMD + dst_sm[i], 1);
        atomicAdd(cnt + C_SMS + src_sm[i], 1);
    }
    if (i < E_RM) {
        atomicAdd(cnt + C_RMD + dst_rm[i], 1);
        atomicAdd(cnt + C_RMS + src_rm[i], 1);
    }
    if (i < E_SIM) {
        atomicAdd(cnt + C_SIMD + dst_sim[i], 1);
        atomicAdd(cnt + C_SIMS + src_sim[i], 1);
    }
}

// 6 blocks, one exclusive scan each
__global__ void scan6_kernel(int* ib) {
    __shared__ int sums[1024];
    const size_t c_ofs[6] = { C_SMD, C_SMS, C_RMD, C_RMS, C_SIMD, C_SIMS };
    const size_t o_ofs[6] = { O_SMD, O_SMS, O_RMD, O_RMS, O_SIMD, O_SIMS };
    const int    ns[6]    = { NM, NS, NM, NR, NM, NM };
    int b = blockIdx.x;
    const int* cnt = ib + IOFF_CNT + c_ofs[b];
    int* off = ib + IOFF_OFF + o_ofs[b];
    int n = ns[b];
    int t = threadIdx.x;
    int chunk = (n + 1023) >> 10;
    int lo = t * chunk, hi = min(lo + chunk, n);
    int s = 0;
    for (int i = lo; i < hi; i++) s += cnt[i];
    sums[t] = s;
    __syncthreads();
    for (int d = 1; d < 1024; d <<= 1) {
        int v = (t >= d) ? sums[t - d] : 0;
        __syncthreads();
        sums[t] += v;
        __syncthreads();
    }
    int run = (t == 0) ? 0 : sums[t - 1];
    for (int i = lo; i < hi; i++) { off[i] = run; run += cnt[i]; }
    if (t == 1023) off[n] = sums[1023];
}

__global__ void fill6_kernel(const int* __restrict__ src_sm, const int* __restrict__ dst_sm,
                             const int* __restrict__ src_rm, const int* __restrict__ dst_rm,
                             const int* __restrict__ src_sim, const int* __restrict__ dst_sim,
                             int* cur, int* pay) {
    int i = blockIdx.x * blockDim.x + threadIdx.x;
    if (i < E_SM) {
        int s = src_sm[i], d = dst_sm[i];
        pay[P_SMD + atomicAdd(cur + O_SMD + d, 1)] = s;
        pay[P_SMS + atomicAdd(cur + O_SMS + s, 1)] = d;
    }
    if (i < E_RM) {
        int s = src_rm[i], d = dst_rm[i];
        pay[P_RMD + atomicAdd(cur + O_RMD + d, 1)] = s;
        pay[P_RMS + atomicAdd(cur + O_RMS + s, 1)] = d;
    }
    if (i < E_SIM) {
        int s = src_sim[i], d = dst_sim[i];
        pay[P_SIMD + atomicAdd(cur + O_SIMD + d, 1)] = s;
        pay[P_SIMS + atomicAdd(cur + O_SIMS + s, 1)] = d;
    }
}

__global__ void make_dv_kernel(const int* __restrict__ off_d, const int* __restrict__ off_s,
                               float* dvf, float* dvr, int n) {
    int i = blockIdx.x * blockDim.x + threadIdx.x;
    if (i < n) {
        dvf[i] = rsqrtf((float)(off_d[i + 1] - off_d[i] + 1));
        dvr[i] = rsqrtf((float)(off_s[i + 1] - off_s[i] + 1));
    }
}

// ---------------- small elementwise ----------------
__global__ void add2_kernel(const float* __restrict__ a, const float* __restrict__ b,
                            float* o, int n) {
    int i = blockIdx.x * blockDim.x + threadIdx.x;
    if (i < n) o[i] = a[i] + b[i];
}

__global__ void add4_kernel(const float* __restrict__ a, const float* __restrict__ b,
                            const float* __restrict__ c, const float* __restrict__ d,
                            float* o, int n) {
    int i = blockIdx.x * blockDim.x + threadIdx.x;
    if (i < n) o[i] = a[i] + b[i] + c[i] + d[i];
}

// ---------------- gather-reduce kernels (warp per node) ----------------
__device__ __forceinline__ void acc4(float4& a, const float4 v) {
    a.x += v.x; a.y += v.y; a.z += v.z; a.w += v.w;
}
__device__ __forceinline__ void fma4(float4& a, float w, const float4 v) {
    a.x = fmaf(w, v.x, a.x); a.y = fmaf(w, v.y, a.y);
    a.z = fmaf(w, v.z, a.z); a.w = fmaf(w, v.w, a.w);
}

__device__ __forceinline__ float4 mean_gather(const float* __restrict__ x,
                                              const int* __restrict__ pay,
                                              int lo, int hi, int c) {
    float4 a = make_float4(0.f, 0.f, 0.f, 0.f);
    int j = lo;
    for (; j + 1 < hi; j += 2) {
        int s0 = __ldg(&pay[j]);
        int s1 = __ldg(&pay[j + 1]);
        float4 v0 = *(const float4*)(x + (size_t)s0 * H + c);
        float4 v1 = *(const float4*)(x + (size_t)s1 * H + c);
        acc4(a, v0); acc4(a, v1);
    }
    if (j < hi) {
        int s0 = __ldg(&pay[j]);
        acc4(a, *(const float4*)(x + (size_t)s0 * H + c));
    }
    float sc = 1.0f / fmaxf((float)(hi - lo), 1.0f);
    a.x *= sc; a.y *= sc; a.z *= sc; a.w *= sc;
    return a;
}

// fused m-side aggregation: SAGE(s->m), SAGE(r->m), GCN both directions (+self loops)
__global__ void __launch_bounds__(256)
m_gather_kernel(const float* __restrict__ xs, const float* __restrict__ xr,
                const float* __restrict__ xw0, const float* __restrict__ xw1,
                const float* __restrict__ dvf, const float* __restrict__ dvr,
                const int* __restrict__ ib_off, const int* __restrict__ ib_pay,
                float* aggsm, float* aggrm, float* accm) {
    int node = (blockIdx.x * blockDim.x + threadIdx.x) >> 5;
    int lane = threadIdx.x & 31;
    if (node >= NM) return;
    int c = lane * 4;
    size_t rowoff = (size_t)node * H + c;

    // SAGE s->m
    {
        int lo = __ldg(&ib_off[O_SMD + node]), hi = __ldg(&ib_off[O_SMD + node + 1]);
        float4 a = mean_gather(xs, ib_pay + P_SMD, lo, hi, c);
        *(float4*)(aggsm + rowoff) = a;
    }
    // SAGE r->m
    {
        int lo = __ldg(&ib_off[O_RMD + node]), hi = __ldg(&ib_off[O_RMD + node + 1]);
        float4 a = mean_gather(xr, ib_pay + P_RMD, lo, hi, c);
        *(float4*)(aggrm + rowoff) = a;
    }
    // GCN forward + reverse (+ self loops)
    {
        float df = __ldg(&dvf[node]);
        float dr = __ldg(&dvr[node]);
        float4 g = make_float4(0.f, 0.f, 0.f, 0.f);
        float4 v0 = *(const float4*)(xw0 + rowoff);
        float4 v1 = *(const float4*)(xw1 + rowoff);
        fma4(g, df * df, v0);
        fma4(g, dr * dr, v1);
        int lo = __ldg(&ib_off[O_SIMD + node]), hi = __ldg(&ib_off[O_SIMD + node + 1]);
        const int* pf = ib_pay + P_SIMD;
        int j = lo;
        for (; j + 1 < hi; j += 2) {
            int s0 = __ldg(&pf[j]);
            int s1 = __ldg(&pf[j + 1]);
            float w0 = df * __ldg(&dvf[s0]);
            float w1 = df * __ldg(&dvf[s1]);
            float4 a0 = *(const float4*)(xw0 + (size_t)s0 * H + c);
            float4 a1 = *(const float4*)(xw0 + (size_t)s1 * H + c);
            fma4(g, w0, a0); fma4(g, w1, a1);
        }
        if (j < hi) {
            int s0 = __ldg(&pf[j]);
            fma4(g, df * __ldg(&dvf[s0]), *(const float4*)(xw0 + (size_t)s0 * H + c));
        }
        lo = __ldg(&ib_off[O_SIMS + node]); hi = __ldg(&ib_off[O_SIMS + node + 1]);
        const int* pr = ib_pay + P_SIMS;
        j = lo;
        for (; j + 1 < hi; j += 2) {
            int t0 = __ldg(&pr[j]);
            int t1 = __ldg(&pr[j + 1]);
            float w0 = dr * __ldg(&dvr[t0]);
            float w1 = dr * __ldg(&dvr[t1]);
            float4 a0 = *(const float4*)(xw1 + (size_t)t0 * H + c);
            float4 a1 = *(const float4*)(xw1 + (size_t)t1 * H + c);
            fma4(g, w0, a0); fma4(g, w1, a1);
        }
        if (j < hi) {
            int t0 = __ldg(&pr[j]);
            fma4(g, dr * __ldg(&dvr[t0]), *(const float4*)(xw1 + (size_t)t0 * H + c));
        }
        *(float4*)(accm + rowoff) = g;
    }
}

// generic mean gather (for s and r sides; source = x_m)
__global__ void __launch_bounds__(256)
gather_mean_kernel(const float* __restrict__ xsrc, const int* __restrict__ off,
                   const int* __restrict__ pay, float* out, int n) {
    int node = (blockIdx.x * blockDim.x + threadIdx.x) >> 5;
    int lane = threadIdx.x & 31;
    if (node >= n) return;
    int c = lane * 4;
    int lo = __ldg(&off[node]), hi = __ldg(&off[node + 1]);
    float4 a = mean_gather(xsrc, pay, lo, hi, c);
    *(float4*)(out + (size_t)node * H + c) = a;
}

// ---------------- 3xTF32 tensor-core multi-phase GEMM ----------------
// C[128 x 128 tile] = relu?( sum_p A_p @ B_p + D + bias )
// Split x = hi + lo (tf32-rounded); D += hi*hi + hi*lo + lo*hi (drop lo*lo).
#define APITCH_TC 36          // floats per A row (KC=32 + pad 4): conflict-free frag loads
#define BPITCH_TC 132         // floats per B row (N=128 + pad 4)
#define KC 32                 // K chunk per smem stage
// smem float offsets
#define S_AHI 0
#define S_ALO (128 * APITCH_TC)
#define S_BHI (2 * 128 * APITCH_TC)
#define S_BLO (2 * 128 * APITCH_TC + KC * BPITCH_TC)
#define GEMM_TC_SMEM ((2 * 128 * APITCH_TC + 2 * KC * BPITCH_TC) * 4)

__device__ __forceinline__ uint32_t f2tf32(float x) {
    uint32_t r;
    asm("cvt.rna.tf32.f32 %0, %1;" : "=r"(r) : "f"(x));
    return r;
}

__device__ __forceinline__ void mma_tf32(float* c, const uint32_t* a, const uint32_t* b) {
    asm volatile(
        "mma.sync.aligned.m16n8k8.row.col.f32.tf32.tf32.f32 "
        "{%0,%1,%2,%3}, {%4,%5,%6,%7}, {%8,%9}, {%0,%1,%2,%3};"
        : "+f"(c[0]), "+f"(c[1]), "+f"(c[2]), "+f"(c[3])
        : "r"(a[0]), "r"(a[1]), "r"(a[2]), "r"(a[3]), "r"(b[0]), "r"(b[1]));
}

__global__ void __launch_bounds__(256)
gemm_tc(int M, int np,
        const float* A0, const float* B0,
        const float* A1, const float* B1,
        const float* A2, const float* B2,
        const float* D, const float* bias, int do_relu, float* C) {
    extern __shared__ float smem[];
    uint32_t* ahi = (uint32_t*)(smem + S_AHI);
    uint32_t* alo = (uint32_t*)(smem + S_ALO);
    uint32_t* bhi = (uint32_t*)(smem + S_BHI);
    uint32_t* blo = (uint32_t*)(smem + S_BLO);

    int tid  = threadIdx.x;
    int wid  = tid >> 5;
    int lane = tid & 31;
    int gid  = lane >> 2;       // 0..7
    int tig  = lane & 3;        // 0..3
    int wy   = wid >> 2;        // 0..1  (warp tile rows: 64)
    int wx   = wid & 3;         // 0..3  (warp tile cols: 32)
    int row0 = blockIdx.x * 128;

    float acc[16][4];           // [mi*4+ni][reg]
#pragma unroll
    for (int f = 0; f < 16; f++)
#pragma unroll
        for (int r = 0; r < 4; r++) acc[f][r] = 0.0f;

    for (int p = 0; p < np; p++) {
        const float *A, *Bw;
        if (p == 0)      { A = A0; Bw = B0; }
        else if (p == 1) { A = A1; Bw = B1; }
        else             { A = A2; Bw = B2; }

#pragma unroll 1
        for (int kc4 = 0; kc4 < H / KC; kc4++) {
            int kc = kc4 * KC;
            __syncthreads();
            // ---- load + split A stage: 128 rows x KC cols ----
#pragma unroll
            for (int it = 0; it < 4; it++) {
                int lin = tid + it * 256;        // 0..1023 float4 slots
                int m   = lin >> 3;              // 8 float4 per row
                int k4  = (lin & 7) << 2;
                int grow = row0 + m;
                float4 v = make_float4(0.f, 0.f, 0.f, 0.f);
                if (grow < M) v = *(const float4*)(A + (size_t)grow * H + kc + k4);
                uint32_t h0 = f2tf32(v.x), h1 = f2tf32(v.y),
                         h2 = f2tf32(v.z), h3 = f2tf32(v.w);
                uint32_t l0 = f2tf32(v.x - __uint_as_float(h0));
                uint32_t l1 = f2tf32(v.y - __uint_as_float(h1));
                uint32_t l2 = f2tf32(v.z - __uint_as_float(h2));
                uint32_t l3 = f2tf32(v.w - __uint_as_float(h3));
                uint4* dsth = (uint4*)(ahi + m * APITCH_TC + k4);
                uint4* dstl = (uint4*)(alo + m * APITCH_TC + k4);
                *dsth = make_uint4(h0, h1, h2, h3);
                *dstl = make_uint4(l0, l1, l2, l3);
            }
            // ---- load + split B stage: KC rows x 128 cols ----
#pragma unroll
            for (int it = 0; it < 4; it++) {
                int lin = tid + it * 256;
                int kr  = lin >> 5;              // 32 float4 per row
                int c4  = (lin & 31) << 2;
                float4 v = *(const float4*)(Bw + (size_t)(kc + kr) * H + c4);
                uint32_t h0 = f2tf32(v.x), h1 = f2tf32(v.y),
                         h2 = f2tf32(v.z), h3 = f2tf32(v.w);
                uint32_t l0 = f2tf32(v.x - __uint_as_float(h0));
                uint32_t l1 = f2tf32(v.y - __uint_as_float(h1));
                uint32_t l2 = f2tf32(v.z - __uint_as_float(h2));
                uint32_t l3 = f2tf32(v.w - __uint_as_float(h3));
                uint4* dsth = (uint4*)(bhi + kr * BPITCH_TC + c4);
                uint4* dstl = (uint4*)(blo + kr * BPITCH_TC + c4);
                *dsth = make_uint4(h0, h1, h2, h3);
                *dstl = make_uint4(l0, l1, l2, l3);
            }
            __syncthreads();

            // ---- compute: KC/8 k-steps ----
#pragma unroll
            for (int k8 = 0; k8 < KC / 8; k8++) {
                int kk = k8 * 8;
                uint32_t Ah[4][4], Al[4][4], Bh[4][2], Bl[4][2];
#pragma unroll
                for (int mi = 0; mi < 4; mi++) {
                    int r0 = wy * 64 + mi * 16 + gid;
                    int r8 = r0 + 8;
                    Ah[mi][0] = ahi[r0 * APITCH_TC + kk + tig];
                    Ah[mi][1] = ahi[r8 * APITCH_TC + kk + tig];
                    Ah[mi][2] = ahi[r0 * APITCH_TC + kk + tig + 4];
                    Ah[mi][3] = ahi[r8 * APITCH_TC + kk + tig + 4];
                    Al[mi][0] = alo[r0 * APITCH_TC + kk + tig];
                    Al[mi][1] = alo[r8 * APITCH_TC + kk + tig];
                    Al[mi][2] = alo[r0 * APITCH_TC + kk + tig + 4];
                    Al[mi][3] = alo[r8 * APITCH_TC + kk + tig + 4];
                }
#pragma unroll
                for (int ni = 0; ni < 4; ni++) {
                    int cc = wx * 32 + ni * 8 + gid;
                    Bh[ni][0] = bhi[(kk + tig) * BPITCH_TC + cc];
                    Bh[ni][1] = bhi[(kk + tig + 4) * BPITCH_TC + cc];
                    Bl[ni][0] = blo[(kk + tig) * BPITCH_TC + cc];
                    Bl[ni][1] = blo[(kk + tig + 4) * BPITCH_TC + cc];
                }
#pragma unroll
                for (int mi = 0; mi < 4; mi++)
#pragma unroll
                    for (int ni = 0; ni < 4; ni++) {
                        float* c = acc[mi * 4 + ni];
                        mma_tf32(c, Ah[mi], Bh[ni]);   // hi*hi
                        mma_tf32(c, Ah[mi], Bl[ni]);   // hi*lo
                        mma_tf32(c, Al[mi], Bh[ni]);   // lo*hi
                    }
            }
        }
        __syncthreads();
    }

    // ---- epilogue: c0=(gid, 2tig), c1=(gid, 2tig+1), c2=(gid+8, 2tig), c3 ----
#pragma unroll
    for (int mi = 0; mi < 4; mi++) {
#pragma unroll
        for (int ni = 0; ni < 4; ni++) {
            const float* c = acc[mi * 4 + ni];
            int col = wx * 32 + ni * 8 + tig * 2;
            int ra  = row0 + wy * 64 + mi * 16 + gid;
            int rb  = ra + 8;
            float2 v0 = make_float2(c[0], c[1]);
            float2 v1 = make_float2(c[2], c[3]);
            if (bias) {
                float2 bs = *(const float2*)(bias + col);
                v0.x += bs.x; v0.y += bs.y;
                v1.x += bs.x; v1.y += bs.y;
            }
            if (ra < M) {
                if (D) {
                    float2 d = *(const float2*)(D + (size_t)ra * H + col);
                    v0.x += d.x; v0.y += d.y;
                }
                if (do_relu) { v0.x = fmaxf(v0.x, 0.f); v0.y = fmaxf(v0.y, 0.f); }
                *(float2*)(C + (size_t)ra * H + col) = v0;
            }
            if (rb < M) {
                if (D) {
                    float2 d = *(const float2*)(D + (size_t)rb * H + col);
                    v1.x += d.x; v1.y += d.y;
                }
                if (do_relu) { v1.x = fmaxf(v1.x, 0.f); v1.y = fmaxf(v1.y, 0.f); }
                *(float2*)(C + (size_t)rb * H + col) = v1;
            }
        }
    }
}

// ---------------- final link prediction ----------------
__global__ void predict_kernel(const float* __restrict__ xs, const float* __restrict__ xm,
                               const float* __restrict__ xr,
                               const int* __restrict__ ls, const int* __restrict__ lm,
                               const int* __restrict__ lr, float* out, int Ln) {
    int lane = threadIdx.x & 31;
    int warp = (blockIdx.x * blockDim.x + threadIdx.x) >> 5;
    if (warp >= Ln) return;
    int is = ls[warp], im = lm[warp], ir = lr[warp];
    float4 m = *(const float4*)(xm + (size_t)im * H + lane * 4);
    float4 s = *(const float4*)(xs + (size_t)is * H + lane * 4);
    float4 r = *(const float4*)(xr + (size_t)ir * H + lane * 4);
    float ds = s.x * m.x + s.y * m.y + s.z * m.z + s.w * m.w;
    float dr = r.x * m.x + r.y * m.y + r.z * m.z + r.w * m.w;
#pragma unroll
    for (int o = 16; o; o >>= 1) {
        ds += __shfl_xor_sync(0xffffffffu, ds, o);
        dr += __shfl_xor_sync(0xffffffffu, dr, o);
    }
    if (lane == 0) {
        out[warp] = ds;
        out[Ln + warp] = dr;
    }
}

// ---------------- host orchestration ----------------
static inline void gemm(int M, int np,
                        const float* A0, const float* B0,
                        const float* A1, const float* B1,
                        const float* A2, const float* B2,
                        const float* D, const float* bias, int relu, float* C) {
    gemm_tc<<<(M + 127) / 128, 256, GEMM_TC_SMEM>>>(M, np, A0, B0, A1, B1, A2, B2,
                                                    D, bias, relu, C);
}

extern "C" void kernel_launch(void* const* d_in, const int* in_sizes, int n_in,
                              void* d_out, int out_size) {
    (void)in_sizes; (void)n_in; (void)out_size;

    const float* emb_s = (const float*)d_in[0];
    const float* emb_m = (const float*)d_in[1];
    const float* emb_r = (const float*)d_in[2];
    const float* Wl    = (const float*)d_in[3];   // [2,4,H,H]
    const float* bl    = (const float*)d_in[4];   // [2,4,H]
    const float* Wr    = (const float*)d_in[5];   // [2,4,H,H]
    const float* Wg    = (const float*)d_in[6];   // [2,2,H,H]
    const float* bg    = (const float*)d_in[7];   // [2,2,H]
    const int* src_sm  = (const int*)d_in[8];
    const int* dst_sm  = (const int*)d_in[9];
    const int* src_rm  = (const int*)d_in[10];
    const int* dst_rm  = (const int*)d_in[11];
    const int* src_sim = (const int*)d_in[12];
    const int* dst_sim = (const int*)d_in[13];
    const int* lbl_s   = (const int*)d_in[14];
    const int* lbl_m   = (const int*)d_in[15];
    const int* lbl_r   = (const int*)d_in[16];
    float* out = (float*)d_out;

    float* fb = nullptr;
    int* ib = nullptr;
    cudaGetSymbolAddress((void**)&fb, g_fbuf);
    cudaGetSymbolAddress((void**)&ib, g_ibuf);

    float* xs[2]  = { fb + OFF_XS0, fb + OFF_XS1 };
    float* xm[2]  = { fb + OFF_XM0, fb + OFF_XM1 };
    float* xr[2]  = { fb + OFF_XR0, fb + OFF_XR1 };
    float* xw0    = fb + OFF_XW0;
    float* xw1    = fb + OFF_XW1;
    float* accm   = fb + OFF_ACCM;
    float* aggsm  = fb + OFF_AGGSM;
    float* aggrm  = fb + OFF_AGGRM;
    float* aggs   = fb + OFF_AGGS;
    float* aggr   = fb + OFF_AGGR;
    float* wrsum  = fb + OFF_WRSUM;
    float* biasm  = fb + OFF_BIASM;
    float* dvf    = fb + OFF_DVF;
    float* dvr    = fb + OFF_DVR;

    int* ib_cnt = ib + IOFF_CNT;
    int* ib_off = ib + IOFF_OFF;
    int* ib_cur = ib + IOFF_CUR;
    int* ib_pay = ib + IOFF_PAY;

    cudaFuncSetAttribute(gemm_tc, cudaFuncAttributeMaxDynamicSharedMemorySize, GEMM_TC_SMEM);

    const int TPB = 256;

    // ---- CSR build (edge structure only; reused by both layers) ----
    cudaMemsetAsync(ib_cnt, 0, CNT_TOT * sizeof(int));
    count6_kernel<<<(E_SM + TPB - 1) / TPB, TPB>>>(src_sm, dst_sm, src_rm, dst_rm,
                                                   src_sim, dst_sim, ib_cnt);
    scan6_kernel<<<6, 1024>>>(ib);
    cudaMemcpyAsync(ib_cur, ib_off, OFF_TOT * sizeof(int), cudaMemcpyDeviceToDevice);
    fill6_kernel<<<(E_SM + TPB - 1) / TPB, TPB>>>(src_sm, dst_sm, src_rm, dst_rm,
                                                  src_sim, dst_sim, ib_cur, ib_pay);
    make_dv_kernel<<<(NM + TPB - 1) / TPB, TPB>>>(ib_off + O_SIMD, ib_off + O_SIMS,
                                                  dvf, dvr, NM);

    const float* cxs = emb_s;
    const float* cxm = emb_m;
    const float* cxr = emb_r;

    for (int l = 0; l < 2; l++) {
        const float* Wl0 = Wl + (size_t)(l * 4 + 0) * H * H;
        const float* Wl1 = Wl + (size_t)(l * 4 + 1) * H * H;
        const float* Wl2 = Wl + (size_t)(l * 4 + 2) * H * H;
        const float* Wl3 = Wl + (size_t)(l * 4 + 3) * H * H;
        const float* Wr1 = Wr + (size_t)(l * 4 + 1) * H * H;
        const float* Wr3 = Wr + (size_t)(l * 4 + 3) * H * H;
        const float* Wr0 = Wr + (size_t)(l * 4 + 0) * H * H;
        const float* Wr2 = Wr + (size_t)(l * 4 + 2) * H * H;
        const float* bl0 = bl + (size_t)(l * 4 + 0) * H;
        const float* bl1 = bl + (size_t)(l * 4 + 1) * H;
        const float* bl2 = bl + (size_t)(l * 4 + 2) * H;
        const float* bl3 = bl + (size_t)(l * 4 + 3) * H;
        const float* Wg0 = Wg + (size_t)(l * 2 + 0) * H * H;
        const float* Wg1 = Wg + (size_t)(l * 2 + 1) * H * H;
        const float* bg0 = bg + (size_t)(l * 2 + 0) * H;
        const float* bg1 = bg + (size_t)(l * 2 + 1) * H;

        // GCN transforms
        gemm(NM, 1, cxm, Wg0, nullptr, nullptr, nullptr, nullptr,
             nullptr, nullptr, 0, xw0);
        gemm(NM, 1, cxm, Wg1, nullptr, nullptr, nullptr, nullptr,
             nullptr, nullptr, 0, xw1);

        // combined bias (bl0+bl2+bg0+bg1) and Wr0+Wr2
        add4_kernel<<<1, H>>>(bl0, bl2, bg0, bg1, biasm, H);
        add2_kernel<<<(H * H + TPB - 1) / TPB, TPB>>>(Wr0, Wr2, wrsum, H * H);

        // fused m-side aggregation (SAGE s->m, SAGE r->m, GCN both dirs + self loops)
        m_gather_kernel<<<(NM * 32 + TPB - 1) / TPB, TPB>>>(cxs, cxr, xw0, xw1, dvf, dvr,
                                                            ib_off, ib_pay,
                                                            aggsm, aggrm, accm);
        // s- and r-side SAGE aggregations (gather from x_m)
        gather_mean_kernel<<<(NS * 32 + TPB - 1) / TPB, TPB>>>(cxm, ib_off + O_SMS,
                                                               ib_pay + P_SMS, aggs, NS);
        gather_mean_kernel<<<(NR * 32 + TPB - 1) / TPB, TPB>>>(cxm, ib_off + O_RMS,
                                                               ib_pay + P_RMS, aggr, NR);

        // fused output GEMMs (+ ReLU)
        gemm(NM, 3, aggsm, Wl0, aggrm, Wl2, cxm, wrsum, accm, biasm, 1, xm[l]);
        gemm(NS, 2, aggs, Wl1, cxs, Wr1, nullptr, nullptr, nullptr, bl1, 1, xs[l]);
        gemm(NR, 2, aggr, Wl3, cxr, Wr3, nullptr, nullptr, nullptr, bl3, 1, xr[l]);

        cxs = xs[l]; cxm = xm[l]; cxr = xr[l];
    }

    predict_kernel<<<(NLBL * 32 + TPB - 1) / TPB, TPB>>>(cxs, cxm, cxr,
                                                         lbl_s, lbl_m, lbl_r, out, NLBL);
}

// round 13
// speedup vs baseline: 1.5641x; 1.0521x over previous
#include <cuda_runtime.h>
#include <cstdint>

#define NS 5000
#define NM 100000
#define NR 2000
#define H  128
#define E_SM  2000000
#define E_RM  1000000
#define E_SIM 2000000
#define NLBL  500000

// ---------------- static device scratch (no cudaMalloc allowed) ----------------
static constexpr size_t SZ_S = (size_t)NS * H;
static constexpr size_t SZ_M = (size_t)NM * H;
static constexpr size_t SZ_R = (size_t)NR * H;

static constexpr size_t OFF_XS0   = 0;
static constexpr size_t OFF_XS1   = OFF_XS0 + SZ_S;
static constexpr size_t OFF_XR0   = OFF_XS1 + SZ_S;
static constexpr size_t OFF_XR1   = OFF_XR0 + SZ_R;
static constexpr size_t OFF_AGGS  = OFF_XR1 + SZ_R;
static constexpr size_t OFF_AGGR  = OFF_AGGS + SZ_S;
static constexpr size_t OFF_XM0   = OFF_AGGR + SZ_R;
static constexpr size_t OFF_XM1   = OFF_XM0 + SZ_M;
static constexpr size_t OFF_XW0   = OFF_XM1 + SZ_M;
static constexpr size_t OFF_XW1   = OFF_XW0 + SZ_M;
static constexpr size_t OFF_ACCM  = OFF_XW1 + SZ_M;
static constexpr size_t OFF_AGGSM = OFF_ACCM + SZ_M;
static constexpr size_t OFF_AGGRM = OFF_AGGSM + SZ_M;
static constexpr size_t OFF_WRSUM = OFF_AGGRM + SZ_M;
static constexpr size_t OFF_BIASM = OFF_WRSUM + (size_t)H * H;
static constexpr size_t OFF_DVF   = OFF_BIASM + H;
static constexpr size_t OFF_DVR   = OFF_DVF + NM;
static constexpr size_t TOTF      = OFF_DVR + NM;

__device__ float g_fbuf[TOTF];

// ---- int scratch: counts, CSR offsets, cursors, payloads ----
static constexpr size_t C_SMD  = 0;
static constexpr size_t C_SMS  = C_SMD + NM;
static constexpr size_t C_RMD  = C_SMS + NS;
static constexpr size_t C_RMS  = C_RMD + NM;
static constexpr size_t C_SIMD = C_RMS + NR;
static constexpr size_t C_SIMS = C_SIMD + NM;
static constexpr size_t CNT_TOT = C_SIMS + NM;

static constexpr size_t O_SMD  = 0;
static constexpr size_t O_SMS  = O_SMD + NM + 1;
static constexpr size_t O_RMD  = O_SMS + NS + 1;
static constexpr size_t O_RMS  = O_RMD + NM + 1;
static constexpr size_t O_SIMD = O_RMS + NR + 1;
static constexpr size_t O_SIMS = O_SIMD + NM + 1;
static constexpr size_t OFF_TOT = O_SIMS + NM + 1;

static constexpr size_t P_SMD  = 0;
static constexpr size_t P_SMS  = P_SMD + E_SM;
static constexpr size_t P_RMD  = P_SMS + E_SM;
static constexpr size_t P_RMS  = P_RMD + E_RM;
static constexpr size_t P_SIMD = P_RMS + E_RM;
static constexpr size_t P_SIMS = P_SIMD + E_SIM;
static constexpr size_t PAY_TOT = P_SIMS + E_SIM;

static constexpr size_t IOFF_CNT = 0;
static constexpr size_t IOFF_OFF = IOFF_CNT + CNT_TOT;
static constexpr size_t IOFF_CUR = IOFF_OFF + OFF_TOT;
static constexpr size_t IOFF_PAY = IOFF_CUR + OFF_TOT;
static constexpr size_t TOTI     = IOFF_PAY + PAY_TOT;

__device__ int g_ibuf[TOTI];

// ---------------- CSR build ----------------
__global__ void count6_kernel(const int* __restrict__ src_sm, const int* __restrict__ dst_sm,
                              const int* __restrict__ src_rm, const int* __restrict__ dst_rm,
                              const int* __restrict__ src_sim, const int* __restrict__ dst_sim,
                              int* cnt) {
    int i = blockIdx.x * blockDim.x + threadIdx.x;
    if (i < E_SM) {
        atomicAdd(cnt + C_SMD + dst_sm[i], 1);
        atomicAdd(cnt + C_SMS + src_sm[i], 1);
    }
    if (i < E_RM) {
        atomicAdd(cnt + C_RMD + dst_rm[i], 1);
        atomicAdd(cnt + C_RMS + src_rm[i], 1);
    }
    if (i < E_SIM) {
        atomicAdd(cnt + C_SIMD + dst_sim[i], 1);
        atomicAdd(cnt + C_SIMS + src_sim[i], 1);
    }
}

// 6 blocks, one exclusive scan each
__global__ void scan6_kernel(int* ib) {
    __shared__ int sums[1024];
    const size_t c_ofs[6] = { C_SMD, C_SMS, C_RMD, C_RMS, C_SIMD, C_SIMS };
    const size_t o_ofs[6] = { O_SMD, O_SMS, O_RMD, O_RMS, O_SIMD, O_SIMS };
    const int    ns[6]    = { NM, NS, NM, NR, NM, NM };
    int b = blockIdx.x;
    const int* cnt = ib + IOFF_CNT + c_ofs[b];
    int* off = ib + IOFF_OFF + o_ofs[b];
    int n = ns[b];
    int t = threadIdx.x;
    int chunk = (n + 1023) >> 10;
    int lo = t * chunk, hi = min(lo + chunk, n);
    int s = 0;
    for (int i = lo; i < hi; i++) s += cnt[i];
    sums[t] = s;
    __syncthreads();
    for (int d = 1; d < 1024; d <<= 1) {
        int v = (t >= d) ? sums[t - d] : 0;
        __syncthreads();
        sums[t] += v;
        __syncthreads();
    }
    int run = (t == 0) ? 0 : sums[t - 1];
    for (int i = lo; i < hi; i++) { off[i] = run; run += cnt[i]; }
    if (t == 1023) off[n] = sums[1023];
}

// fill CSR payloads; threads < NM also derive GCN degree norms (offsets are final here)
__global__ void fill6_kernel(const int* __restrict__ src_sm, const int* __restrict__ dst_sm,
                             const int* __restrict__ src_rm, const int* __restrict__ dst_rm,
                             const int* __restrict__ src_sim, const int* __restrict__ dst_sim,
                             const int* __restrict__ off, int* cur, int* pay,
                             float* dvf, float* dvr) {
    int i = blockIdx.x * blockDim.x + threadIdx.x;
    if (i < NM) {
        dvf[i] = rsqrtf((float)(off[O_SIMD + i + 1] - off[O_SIMD + i] + 1));
        dvr[i] = rsqrtf((float)(off[O_SIMS + i + 1] - off[O_SIMS + i] + 1));
    }
    if (i < E_SM) {
        int s = src_sm[i], d = dst_sm[i];
        pay[P_SMD + atomicAdd(cur + O_SMD + d, 1)] = s;
        pay[P_SMS + atomicAdd(cur + O_SMS + s, 1)] = d;
    }
    if (i < E_RM) {
        int s = src_rm[i], d = dst_rm[i];
        pay[P_RMD + atomicAdd(cur + O_RMD + d, 1)] = s;
        pay[P_RMS + atomicAdd(cur + O_RMS + s, 1)] = d;
    }
    if (i < E_SIM) {
        int s = src_sim[i], d = dst_sim[i];
        pay[P_SIMD + atomicAdd(cur + O_SIMD + d, 1)] = s;
        pay[P_SIMS + atomicAdd(cur + O_SIMS + s, 1)] = d;
    }
}

// ---------------- small elementwise ----------------
__global__ void add2_kernel(const float* __restrict__ a, const float* __restrict__ b,
                            float* o, int n) {
    int i = blockIdx.x * blockDim.x + threadIdx.x;
    if (i < n) o[i] = a[i] + b[i];
}

__global__ void add4_kernel(const float* __restrict__ a, const float* __restrict__ b,
                            const float* __restrict__ c, const float* __restrict__ d,
                            float* o, int n) {
    int i = blockIdx.x * blockDim.x + threadIdx.x;
    if (i < n) o[i] = a[i] + b[i] + c[i] + d[i];
}

// ---------------- gather-reduce kernels (warp per node) ----------------
__device__ __forceinline__ void acc4(float4& a, const float4 v) {
    a.x += v.x; a.y += v.y; a.z += v.z; a.w += v.w;
}
__device__ __forceinline__ void fma4(float4& a, float w, const float4 v) {
    a.x = fmaf(w, v.x, a.x); a.y = fmaf(w, v.y, a.y);
    a.z = fmaf(w, v.z, a.z); a.w = fmaf(w, v.w, a.w);
}

__device__ __forceinline__ float4 mean_gather(const float* __restrict__ x,
                                              const int* __restrict__ pay,
                                              int lo, int hi, int c) {
    float4 a = make_float4(0.f, 0.f, 0.f, 0.f);
    int j = lo;
    for (; j + 1 < hi; j += 2) {
        int s0 = __ldg(&pay[j]);
        int s1 = __ldg(&pay[j + 1]);
        float4 v0 = *(const float4*)(x + (size_t)s0 * H + c);
        float4 v1 = *(const float4*)(x + (size_t)s1 * H + c);
        acc4(a, v0); acc4(a, v1);
    }
    if (j < hi) {
        int s0 = __ldg(&pay[j]);
        acc4(a, *(const float4*)(x + (size_t)s0 * H + c));
    }
    float sc = 1.0f / fmaxf((float)(hi - lo), 1.0f);
    a.x *= sc; a.y *= sc; a.z *= sc; a.w *= sc;
    return a;
}

// fused m-side aggregation: SAGE(s->m), SAGE(r->m), GCN both directions (+self loops)
__global__ void __launch_bounds__(256)
m_gather_kernel(const float* __restrict__ xs, const float* __restrict__ xr,
                const float* __restrict__ xw0, const float* __restrict__ xw1,
                const float* __restrict__ dvf, const float* __restrict__ dvr,
                const int* __restrict__ ib_off, const int* __restrict__ ib_pay,
                float* aggsm, float* aggrm, float* accm) {
    int node = (blockIdx.x * blockDim.x + threadIdx.x) >> 5;
    int lane = threadIdx.x & 31;
    if (node >= NM) return;
    int c = lane * 4;
    size_t rowoff = (size_t)node * H + c;

    // SAGE s->m
    {
        int lo = __ldg(&ib_off[O_SMD + node]), hi = __ldg(&ib_off[O_SMD + node + 1]);
        float4 a = mean_gather(xs, ib_pay + P_SMD, lo, hi, c);
        *(float4*)(aggsm + rowoff) = a;
    }
    // SAGE r->m
    {
        int lo = __ldg(&ib_off[O_RMD + node]), hi = __ldg(&ib_off[O_RMD + node + 1]);
        float4 a = mean_gather(xr, ib_pay + P_RMD, lo, hi, c);
        *(float4*)(aggrm + rowoff) = a;
    }
    // GCN forward + reverse (+ self loops)
    {
        float df = __ldg(&dvf[node]);
        float dr = __ldg(&dvr[node]);
        float4 g = make_float4(0.f, 0.f, 0.f, 0.f);
        float4 v0 = *(const float4*)(xw0 + rowoff);
        float4 v1 = *(const float4*)(xw1 + rowoff);
        fma4(g, df * df, v0);
        fma4(g, dr * dr, v1);
        int lo = __ldg(&ib_off[O_SIMD + node]), hi = __ldg(&ib_off[O_SIMD + node + 1]);
        const int* pf = ib_pay + P_SIMD;
        int j = lo;
        for (; j + 1 < hi; j += 2) {
            int s0 = __ldg(&pf[j]);
            int s1 = __ldg(&pf[j + 1]);
            float w0 = df * __ldg(&dvf[s0]);
            float w1 = df * __ldg(&dvf[s1]);
            float4 a0 = *(const float4*)(xw0 + (size_t)s0 * H + c);
            float4 a1 = *(const float4*)(xw0 + (size_t)s1 * H + c);
            fma4(g, w0, a0); fma4(g, w1, a1);
        }
        if (j < hi) {
            int s0 = __ldg(&pf[j]);
            fma4(g, df * __ldg(&dvf[s0]), *(const float4*)(xw0 + (size_t)s0 * H + c));
        }
        lo = __ldg(&ib_off[O_SIMS + node]); hi = __ldg(&ib_off[O_SIMS + node + 1]);
        const int* pr = ib_pay + P_SIMS;
        j = lo;
        for (; j + 1 < hi; j += 2) {
            int t0 = __ldg(&pr[j]);
            int t1 = __ldg(&pr[j + 1]);
            float w0 = dr * __ldg(&dvr[t0]);
            float w1 = dr * __ldg(&dvr[t1]);
            float4 a0 = *(const float4*)(xw1 + (size_t)t0 * H + c);
            float4 a1 = *(const float4*)(xw1 + (size_t)t1 * H + c);
            fma4(g, w0, a0); fma4(g, w1, a1);
        }
        if (j < hi) {
            int t0 = __ldg(&pr[j]);
            fma4(g, dr * __ldg(&dvr[t0]), *(const float4*)(xw1 + (size_t)t0 * H + c));
        }
        *(float4*)(accm + rowoff) = g;
    }
}

// generic mean gather (for s and r sides; source = x_m)
__global__ void __launch_bounds__(256)
gather_mean_kernel(const float* __restrict__ xsrc, const int* __restrict__ off,
                   const int* __restrict__ pay, float* out, int n) {
    int node = (blockIdx.x * blockDim.x + threadIdx.x) >> 5;
    int lane = threadIdx.x & 31;
    if (node >= n) return;
    int c = lane * 4;
    int lo = __ldg(&off[node]), hi = __ldg(&off[node + 1]);
    float4 a = mean_gather(xsrc, pay, lo, hi, c);
    *(float4*)(out + (size_t)node * H + c) = a;
}

// ---------------- 3xTF32 tensor-core multi-phase GEMM (register double-buffered) ----
// C[128 x 128 tile] = relu?( sum_p A_p @ B_p + D + bias )
// Split x = hi + lo (tf32-rounded); D += hi*hi + hi*lo + lo*hi (drop lo*lo).
#define APITCH_TC 36          // floats per A row (KC=32 + pad 4)
#define BPITCH_TC 132         // floats per B row (N=128 + pad 4)
#define KC 32                 // K chunk per smem stage
#define S_AHI 0
#define S_ALO (128 * APITCH_TC)
#define S_BHI (2 * 128 * APITCH_TC)
#define S_BLO (2 * 128 * APITCH_TC + KC * BPITCH_TC)
#define GEMM_TC_SMEM ((2 * 128 * APITCH_TC + 2 * KC * BPITCH_TC) * 4)

__device__ __forceinline__ uint32_t f2tf32(float x) {
    uint32_t r;
    asm("cvt.rna.tf32.f32 %0, %1;" : "=r"(r) : "f"(x));
    return r;
}

__device__ __forceinline__ void mma_tf32(float* c, const uint32_t* a, const uint32_t* b) {
    asm volatile(
        "mma.sync.aligned.m16n8k8.row.col.f32.tf32.tf32.f32 "
        "{%0,%1,%2,%3}, {%4,%5,%6,%7}, {%8,%9}, {%0,%1,%2,%3};"
        : "+f"(c[0]), "+f"(c[1]), "+f"(c[2]), "+f"(c[3])
        : "r"(a[0]), "r"(a[1]), "r"(a[2]), "r"(a[3]), "r"(b[0]), "r"(b[1]));
}

__global__ void __launch_bounds__(256)
gemm_tc(int M, int np,
        const float* A0, const float* B0,
        const float* A1, const float* B1,
        const float* A2, const float* B2,
        const float* D, const float* bias, int do_relu, float* C) {
    extern __shared__ float smem[];
    uint32_t* ahi = (uint32_t*)(smem + S_AHI);
    uint32_t* alo = (uint32_t*)(smem + S_ALO);
    uint32_t* bhi = (uint32_t*)(smem + S_BHI);
    uint32_t* blo = (uint32_t*)(smem + S_BLO);

    int tid  = threadIdx.x;
    int wid  = tid >> 5;
    int lane = tid & 31;
    int gid  = lane >> 2;       // 0..7
    int tig  = lane & 3;        // 0..3
    int wy   = wid >> 2;        // 0..1
    int wx   = wid & 3;         // 0..3
    int row0 = blockIdx.x * 128;

    const float* Aps[3] = { A0, A1, A2 };
    const float* Bps[3] = { B0, B1, B2 };

    float acc[16][4];
#pragma unroll
    for (int f = 0; f < 16; f++)
#pragma unroll
        for (int r = 0; r < 4; r++) acc[f][r] = 0.0f;

    float4 ra[4], rb[4];        // prefetch registers for next stage

    auto preload = [&](int t) {
        int p  = t >> 2;
        int kc = (t & 3) * KC;
        const float* A  = Aps[p];
        const float* Bw = Bps[p];
#pragma unroll
        for (int it = 0; it < 4; it++) {
            int lin = tid + it * 256;
            int m   = lin >> 3;
            int k4  = (lin & 7) << 2;
            int grow = row0 + m;
            ra[it] = (grow < M) ? *(const float4*)(A + (size_t)grow * H + kc + k4)
                                : make_float4(0.f, 0.f, 0.f, 0.f);
        }
#pragma unroll
        for (int it = 0; it < 4; it++) {
            int lin = tid + it * 256;
            int kr  = lin >> 5;
            int c4  = (lin & 31) << 2;
            rb[it] = *(const float4*)(Bw + (size_t)(kc + kr) * H + c4);
        }
    };

    int nchunks = np * (H / KC);
    preload(0);

#pragma unroll 1
    for (int t = 0; t < nchunks; t++) {
        __syncthreads();        // previous compute done; smem reusable
        // ---- store + split prefetched registers into smem ----
#pragma unroll
        for (int it = 0; it < 4; it++) {
            int lin = tid + it * 256;
            int m   = lin >> 3;
            int k4  = (lin & 7) << 2;
            float4 v = ra[it];
            uint32_t h0 = f2tf32(v.x), h1 = f2tf32(v.y),
                     h2 = f2tf32(v.z), h3 = f2tf32(v.w);
            uint32_t l0 = f2tf32(v.x - __uint_as_float(h0));
            uint32_t l1 = f2tf32(v.y - __uint_as_float(h1));
            uint32_t l2 = f2tf32(v.z - __uint_as_float(h2));
            uint32_t l3 = f2tf32(v.w - __uint_as_float(h3));
            *(uint4*)(ahi + m * APITCH_TC + k4) = make_uint4(h0, h1, h2, h3);
            *(uint4*)(alo + m * APITCH_TC + k4) = make_uint4(l0, l1, l2, l3);
        }
#pragma unroll
        for (int it = 0; it < 4; it++) {
            int lin = tid + it * 256;
            int kr  = lin >> 5;
            int c4  = (lin & 31) << 2;
            float4 v = rb[it];
            uint32_t h0 = f2tf32(v.x), h1 = f2tf32(v.y),
                     h2 = f2tf32(v.z), h3 = f2tf32(v.w);
            uint32_t l0 = f2tf32(v.x - __uint_as_float(h0));
            uint32_t l1 = f2tf32(v.y - __uint_as_float(h1));
            uint32_t l2 = f2tf32(v.z - __uint_as_float(h2));
            uint32_t l3 = f2tf32(v.w - __uint_as_float(h3));
            *(uint4*)(bhi + kr * BPITCH_TC + c4) = make_uint4(h0, h1, h2, h3);
            *(uint4*)(blo + kr * BPITCH_TC + c4) = make_uint4(l0, l1, l2, l3);
        }
        __syncthreads();        // smem stage ready

        if (t + 1 < nchunks) preload(t + 1);   // overlap next gmem loads with MMA

        // ---- compute: KC/8 k-steps ----
#pragma unroll
        for (int k8 = 0; k8 < KC / 8; k8++) {
            int kk = k8 * 8;
            uint32_t Ah[4][4], Al[4][4], Bh[4][2], Bl[4][2];
#pragma unroll
            for (int mi = 0; mi < 4; mi++) {
                int r0 = wy * 64 + mi * 16 + gid;
                int r8 = r0 + 8;
                Ah[mi][0] = ahi[r0 * APITCH_TC + kk + tig];
                Ah[mi][1] = ahi[r8 * APITCH_TC + kk + tig];
                Ah[mi][2] = ahi[r0 * APITCH_TC + kk + tig + 4];
                Ah[mi][3] = ahi[r8 * APITCH_TC + kk + tig + 4];
                Al[mi][0] = alo[r0 * APITCH_TC + kk + tig];
                Al[mi][1] = alo[r8 * APITCH_TC + kk + tig];
                Al[mi][2] = alo[r0 * APITCH_TC + kk + tig + 4];
                Al[mi][3] = alo[r8 * APITCH_TC + kk + tig + 4];
            }
#pragma unroll
            for (int ni = 0; ni < 4; ni++) {
                int cc = wx * 32 + ni * 8 + gid;
                Bh[ni][0] = bhi[(kk + tig) * BPITCH_TC + cc];
                Bh[ni][1] = bhi[(kk + tig + 4) * BPITCH_TC + cc];
                Bl[ni][0] = blo[(kk + tig) * BPITCH_TC + cc];
                Bl[ni][1] = blo[(kk + tig + 4) * BPITCH_TC + cc];
            }
#pragma unroll
            for (int mi = 0; mi < 4; mi++)
#pragma unroll
                for (int ni = 0; ni < 4; ni++) {
                    float* c = acc[mi * 4 + ni];
                    mma_tf32(c, Ah[mi], Bh[ni]);   // hi*hi
                    mma_tf32(c, Ah[mi], Bl[ni]);   // hi*lo
                    mma_tf32(c, Al[mi], Bh[ni]);   // lo*hi
                }
        }
    }

    // ---- epilogue ----
#pragma unroll
    for (int mi = 0; mi < 4; mi++) {
#pragma unroll
        for (int ni = 0; ni < 4; ni++) {
            const float* c = acc[mi * 4 + ni];
            int col = wx * 32 + ni * 8 + tig * 2;
            int ra_ = row0 + wy * 64 + mi * 16 + gid;
            int rb_ = ra_ + 8;
            float2 v0 = make_float2(c[0], c[1]);
            float2 v1 = make_float2(c[2], c[3]);
            if (bias) {
                float2 bs = *(const float2*)(bias + col);
                v0.x += bs.x; v0.y += bs.y;
                v1.x += bs.x; v1.y += bs.y;
            }
            if (ra_ < M) {
                if (D) {
                    float2 d = *(const float2*)(D + (size_t)ra_ * H + col);
                    v0.x += d.x; v0.y += d.y;
                }
                if (do_relu) { v0.x = fmaxf(v0.x, 0.f); v0.y = fmaxf(v0.y, 0.f); }
                *(float2*)(C + (size_t)ra_ * H + col) = v0;
            }
            if (rb_ < M) {
                if (D) {
                    float2 d = *(const float2*)(D + (size_t)rb_ * H + col);
                    v1.x += d.x; v1.y += d.y;
                }
                if (do_relu) { v1.x = fmaxf(v1.x, 0.f); v1.y = fmaxf(v1.y, 0.f); }
                *(float2*)(C + (size_t)rb_ * H + col) = v1;
            }
        }
    }
}

// ---------------- final link prediction ----------------
__global__ void predict_kernel(const float* __restrict__ xs, const float* __restrict__ xm,
                               const float* __restrict__ xr,
                               const int* __restrict__ ls, const int* __restrict__ lm,
                               const int* __restrict__ lr, float* out, int Ln) {
    int lane = threadIdx.x & 31;
    int warp = (blockIdx.x * blockDim.x + threadIdx.x) >> 5;
    if (warp >= Ln) return;
    int is = ls[warp], im = lm[warp], ir = lr[warp];
    float4 m = *(const float4*)(xm + (size_t)im * H + lane * 4);
    float4 s = *(const float4*)(xs + (size_t)is * H + lane * 4);
    float4 r = *(const float4*)(xr + (size_t)ir * H + lane * 4);
    float ds = s.x * m.x + s.y * m.y + s.z * m.z + s.w * m.w;
    float dr = r.x * m.x + r.y * m.y + r.z * m.z + r.w * m.w;
#pragma unroll
    for (int o = 16; o; o >>= 1) {
        ds += __shfl_xor_sync(0xffffffffu, ds, o);
        dr += __shfl_xor_sync(0xffffffffu, dr, o);
    }
    if (lane == 0) {
        out[warp] = ds;
        out[Ln + warp] = dr;
    }
}

// ---------------- host orchestration ----------------
static inline void gemm(int M, int np,
                        const float* A0, const float* B0,
                        const float* A1, const float* B1,
                        const float* A2, const float* B2,
                        const float* D, const float* bias, int relu, float* C) {
    gemm_tc<<<(M + 127) / 128, 256, GEMM_TC_SMEM>>>(M, np, A0, B0, A1, B1, A2, B2,
                                                    D, bias, relu, C);
}

extern "C" void kernel_launch(void* const* d_in, const int* in_sizes, int n_in,
                              void* d_out, int out_size) {
    (void)in_sizes; (void)n_in; (void)out_size;

    const float* emb_s = (const float*)d_in[0];
    const float* emb_m = (const float*)d_in[1];
    const float* emb_r = (const float*)d_in[2];
    const float* Wl    = (const float*)d_in[3];   // [2,4,H,H]
    const float* bl    = (const float*)d_in[4];   // [2,4,H]
    const float* Wr    = (const float*)d_in[5];   // [2,4,H,H]
    const float* Wg    = (const float*)d_in[6];   // [2,2,H,H]
    const float* bg    = (const float*)d_in[7];   // [2,2,H]
    const int* src_sm  = (const int*)d_in[8];
    const int* dst_sm  = (const int*)d_in[9];
    const int* src_rm  = (const int*)d_in[10];
    const int* dst_rm  = (const int*)d_in[11];
    const int* src_sim = (const int*)d_in[12];
    const int* dst_sim = (const int*)d_in[13];
    const int* lbl_s   = (const int*)d_in[14];
    const int* lbl_m   = (const int*)d_in[15];
    const int* lbl_r   = (const int*)d_in[16];
    float* out = (float*)d_out;

    float* fb = nullptr;
    int* ib = nullptr;
    cudaGetSymbolAddress((void**)&fb, g_fbuf);
    cudaGetSymbolAddress((void**)&ib, g_ibuf);

    float* xs[2]  = { fb + OFF_XS0, fb + OFF_XS1 };
    float* xm[2]  = { fb + OFF_XM0, fb + OFF_XM1 };
    float* xr[2]  = { fb + OFF_XR0, fb + OFF_XR1 };
    float* xw0    = fb + OFF_XW0;
    float* xw1    = fb + OFF_XW1;
    float* accm   = fb + OFF_ACCM;
    float* aggsm  = fb + OFF_AGGSM;
    float* aggrm  = fb + OFF_AGGRM;
    float* aggs   = fb + OFF_AGGS;
    float* aggr   = fb + OFF_AGGR;
    float* wrsum  = fb + OFF_WRSUM;
    float* biasm  = fb + OFF_BIASM;
    float* dvf    = fb + OFF_DVF;
    float* dvr    = fb + OFF_DVR;

    int* ib_cnt = ib + IOFF_CNT;
    int* ib_off = ib + IOFF_OFF;
    int* ib_cur = ib + IOFF_CUR;
    int* ib_pay = ib + IOFF_PAY;

    cudaFuncSetAttribute(gemm_tc, cudaFuncAttributeMaxDynamicSharedMemorySize, GEMM_TC_SMEM);

    const int TPB = 256;

    // ---- CSR build (edge structure only; reused by both layers) ----
    // launch order keeps the first gemm_tc at ncu's skip-5 slot
    cudaMemsetAsync(ib_cnt, 0, CNT_TOT * sizeof(int));
    count6_kernel<<<(E_SM + TPB - 1) / TPB, TPB>>>(src_sm, dst_sm, src_rm, dst_rm,
                                                   src_sim, dst_sim, ib_cnt);
    scan6_kernel<<<6, 1024>>>(ib);
    cudaMemcpyAsync(ib_cur, ib_off, OFF_TOT * sizeof(int), cudaMemcpyDeviceToDevice);
    fill6_kernel<<<(E_SM + TPB - 1) / TPB, TPB>>>(src_sm, dst_sm, src_rm, dst_rm,
                                                  src_sim, dst_sim, ib_off, ib_cur,
                                                  ib_pay, dvf, dvr);

    const float* cxs = emb_s;
    const float* cxm = emb_m;
    const float* cxr = emb_r;

    for (int l = 0; l < 2; l++) {
        const float* Wl0 = Wl + (size_t)(l * 4 + 0) * H * H;
        const float* Wl1 = Wl + (size_t)(l * 4 + 1) * H * H;
        const float* Wl2 = Wl + (size_t)(l * 4 + 2) * H * H;
        const float* Wl3 = Wl + (size_t)(l * 4 + 3) * H * H;
        const float* Wr1 = Wr + (size_t)(l * 4 + 1) * H * H;
        const float* Wr3 = Wr + (size_t)(l * 4 + 3) * H * H;
        const float* Wr0 = Wr + (size_t)(l * 4 + 0) * H * H;
        const float* Wr2 = Wr + (size_t)(l * 4 + 2) * H * H;
        const float* bl0 = bl + (size_t)(l * 4 + 0) * H;
        const float* bl1 = bl + (size_t)(l * 4 + 1) * H;
        const float* bl2 = bl + (size_t)(l * 4 + 2) * H;
        const float* bl3 = bl + (size_t)(l * 4 + 3) * H;
        const float* Wg0 = Wg + (size_t)(l * 2 + 0) * H * H;
        const float* Wg1 = Wg + (size_t)(l * 2 + 1) * H * H;
        const float* bg0 = bg + (size_t)(l * 2 + 0) * H;
        const float* bg1 = bg + (size_t)(l * 2 + 1) * H;

        // GCN transforms
        gemm(NM, 1, cxm, Wg0, nullptr, nullptr, nullptr, nullptr,
             nullptr, nullptr, 0, xw0);
        gemm(NM, 1, cxm, Wg1, nullptr, nullptr, nullptr, nullptr,
             nullptr, nullptr, 0, xw1);

        // combined bias (bl0+bl2+bg0+bg1) and Wr0+Wr2
        add4_kernel<<<1, H>>>(bl0, bl2, bg0, bg1, biasm, H);
        add2_kernel<<<(H * H + TPB - 1) / TPB, TPB>>>(Wr0, Wr2, wrsum, H * H);

        // fused m-side aggregation (SAGE s->m, SAGE r->m, GCN both dirs + self loops)
        m_gather_kernel<<<(NM * 32 + TPB - 1) / TPB, TPB>>>(cxs, cxr, xw0, xw1, dvf, dvr,
                                                            ib_off, ib_pay,
                                                            aggsm, aggrm, accm);
        // s- and r-side SAGE aggregations (gather from x_m)
        gather_mean_kernel<<<(NS * 32 + TPB - 1) / TPB, TPB>>>(cxm, ib_off + O_SMS,
                                                               ib_pay + P_SMS, aggs, NS);
        gather_mean_kernel<<<(NR * 32 + TPB - 1) / TPB, TPB>>>(cxm, ib_off + O_RMS,
                                                               ib_pay + P_RMS, aggr, NR);

        // fused output GEMMs (+ ReLU)
        gemm(NM, 3, aggsm, Wl0, aggrm, Wl2, cxm, wrsum, accm, biasm, 1, xm[l]);
        gemm(NS, 2, aggs, Wl1, cxs, Wr1, nullptr, nullptr, nullptr, bl1, 1, xs[l]);
        gemm(NR, 2, aggr, Wl3, cxr, Wr3, nullptr, nullptr, nullptr, bl3, 1, xr[l]);

        cxs = xs[l]; cxm = xm[l]; cxr = xr[l];
    }

    predict_kernel<<<(NLBL * 32 + TPB - 1) / TPB, TPB>>>(cxs, cxm, cxr,
                                                         lbl_s, lbl_m, lbl_r, out, NLBL);
}